// round 14
// baseline (speedup 1.0000x reference)
#include <cuda_runtime.h>
#include <mma.h>
#include <math.h>
#include <cstdint>

using namespace nvcuda;

#define FD    1024
#define SEM   300
#define NWAY  5
#define BS    32
#define NB    512
#define NQ    75
#define BTOT  (BS*NWAY)     // 160
#define CATD  (FD+SEM)      // 1324

#define MNq   (BTOT*FD)     // 163840
#define MNk   (BTOT*CATD)   // 211840
#define SLABK (BTOT*1408)   // padded qk partial slab
#define SLABG (BS*1408)
#define SLABF (BS*FD)       // 32768

#define SMEMF 12800         // dynamic smem floats (2 x 6400 gemm buffers)
#define BUFF  6400

// ---------------- scratch ----------------
__device__ __align__(32) float g_scal[BTOT*SEM];
__device__ __align__(32) float g_gv  [BS*FD];
__device__ __align__(32) float g_gs  [BS*SEM];
__device__ __align__(32) float g_q   [BTOT*FD];
__device__ __align__(32) float g_qkg [BTOT*FD];
__device__ __align__(32) float g_qksg[BTOT*SEM];
__device__ __align__(32) float g_scr [BTOT*NB];
__device__ __align__(32) float g_avgp[8*BS*CATD];
__device__ __align__(32) float g_mixp[16*SLABF];
__device__ __align__(32) float g_part [16*MNq];
__device__ __align__(32) float g_part2[14*SLABG];
__device__ unsigned int g_barrier;

// ---------------- software grid barrier ----------------
__device__ __forceinline__ void gsync(int &gen)
{
    __syncthreads();
    if (threadIdx.x == 0) {
        __threadfence();
        atomicAdd(&g_barrier, 1u);
        unsigned target = (unsigned)gridDim.x * (unsigned)gen;
        unsigned v;
        do {
            asm volatile("ld.acquire.gpu.u32 %0, [%1];" : "=r"(v) : "l"(&g_barrier) : "memory");
            if (v >= target) break;
            __nanosleep(32);
        } while (true);
    }
    __syncthreads();
    gen++;
}

__device__ __forceinline__ float d4(float4 a, float4 b)
{ return a.x*b.x + a.y*b.y + a.z*b.z + a.w*b.w; }

__device__ __forceinline__ uint64_t mkpolicy()
{
    uint64_t p;
    asm volatile("createpolicy.fractional.L2::evict_last.b64 %0, 1.0;" : "=l"(p));
    return p;
}

// 16B evict-last (policy-register form; bsm rows are only 16B-aligned)
__device__ __forceinline__ float4 ldg_el(const float4* p, uint64_t pol)
{
    float4 v;
    asm volatile("ld.global.L2::cache_hint.v4.f32 {%0,%1,%2,%3}, [%4], %5;"
        : "=f"(v.x), "=f"(v.y), "=f"(v.z), "=f"(v.w) : "l"(p), "l"(pol));
    return v;
}

// 32B evict-last (direct modifier form — legal only on v8.b32)
__device__ __forceinline__ void ldg_el8(const float* p, float4& a, float4& b)
{
    unsigned r0,r1,r2,r3,r4,r5,r6,r7;
    asm volatile("ld.global.L2::evict_last.v8.b32 {%0,%1,%2,%3,%4,%5,%6,%7}, [%8];"
        : "=r"(r0),"=r"(r1),"=r"(r2),"=r"(r3),
          "=r"(r4),"=r"(r5),"=r"(r6),"=r"(r7)
        : "l"(p));
    a.x=__uint_as_float(r0); a.y=__uint_as_float(r1);
    a.z=__uint_as_float(r2); a.w=__uint_as_float(r3);
    b.x=__uint_as_float(r4); b.y=__uint_as_float(r5);
    b.z=__uint_as_float(r6); b.w=__uint_as_float(r7);
}

__device__ __forceinline__ void cp16(uint32_t saddr, const void* g, bool pred)
{
    asm volatile("cp.async.ca.shared.global [%0], [%1], 16, %2;"
        :: "r"(saddr), "l"(g), "r"(pred ? 16 : 0));
}

typedef wmma::fragment<wmma::matrix_a, 16,16,8, wmma::precision::tf32, wmma::row_major> FragA;
typedef wmma::fragment<wmma::matrix_b, 16,16,8, wmma::precision::tf32, wmma::row_major> FragBR;
typedef wmma::fragment<wmma::matrix_b, 16,16,8, wmma::precision::tf32, wmma::col_major> FragBC;
typedef wmma::fragment<wmma::accumulator, 16,16,8, float> FragC;

template<class F>
__device__ __forceinline__ void split_frag(F& hi, F& lo)
{
#pragma unroll
    for (int i = 0; i < hi.num_elements; i++) {
        float r = hi.x[i];
        float h = wmma::__float_to_tf32(r);
        hi.x[i] = h;
        lo.x[i] = wmma::__float_to_tf32(r - h);
    }
}

template<bool BTR>
__device__ __forceinline__ void mma_tile(float* As, float* Bs, int mrow, int nq,
                                         FragC& c0, FragC& c1)
{
#pragma unroll
    for (int kk = 0; kk < 32; kk += 8) {
        FragA ah, al;
        wmma::load_matrix_sync(ah, As + mrow*16*40 + kk, 40);
        split_frag(ah, al);
        if (!BTR) {
            FragBR b0h,b0l,b1h,b1l;
            wmma::load_matrix_sync(b0h, Bs + kk*136 + nq*32, 136);
            wmma::load_matrix_sync(b1h, Bs + kk*136 + nq*32 + 16, 136);
            split_frag(b0h, b0l); split_frag(b1h, b1l);
            wmma::mma_sync(c0, ah, b0h, c0);
            wmma::mma_sync(c0, ah, b0l, c0);
            wmma::mma_sync(c0, al, b0h, c0);
            wmma::mma_sync(c1, ah, b1h, c1);
            wmma::mma_sync(c1, ah, b1l, c1);
            wmma::mma_sync(c1, al, b1h, c1);
        } else {
            FragBC b0h,b0l,b1h,b1l;
            wmma::load_matrix_sync(b0h, Bs + (nq*32)*40 + kk, 40);
            wmma::load_matrix_sync(b1h, Bs + (nq*32+16)*40 + kk, 40);
            split_frag(b0h, b0l); split_frag(b1h, b1l);
            wmma::mma_sync(c0, ah, b0h, c0);
            wmma::mma_sync(c0, ah, b0l, c0);
            wmma::mma_sync(c0, al, b0h, c0);
            wmma::mma_sync(c1, ah, b1h, c1);
            wmma::mma_sync(c1, ah, b1l, c1);
            wmma::mma_sync(c1, al, b1h, c1);
        }
    }
}

template<bool BTR>
__device__ __forceinline__ void gemm_pipe(
    const float* __restrict__ A, int M, int K, int lda,
    const float* __restrict__ B1, const float* __restrict__ B2,
    int N1, int N, int ldb1, int ldb2,
    float* __restrict__ part, size_t slab, int ldp,
    int m0, int n0, int kt0, int kt1, float* __restrict__ smbase)
{
    const int t = threadIdx.x;
    const int warp = t >> 5, mrow = warp >> 2, nq = warp & 3;
    FragC c0, c1;
    wmma::fill_fragment(c0, 0.f);
    wmma::fill_fragment(c1, 0.f);

    auto issue = [&](int kt, int bufi) {
        float* As = smbase + bufi*BUFF;
        float* Bs = As + 1280;
        int k0 = kt*32;
        {
            int mm = t >> 3, kq = t & 7;
            int mg = m0 + mm, kg = k0 + kq*4;
            bool ok = (mg < M) && (kg < K);
            uint32_t sa = (uint32_t)__cvta_generic_to_shared(&As[mm*40 + kq*4]);
            cp16(sa, &A[(size_t)mg*lda + kg], ok);
        }
        if (!BTR) {
            int kk = t >> 3, cc = t & 7;
            int kg = k0 + kk;
#pragma unroll
            for (int j = 0; j < 4; j++) {
                int nn = (cc + 8*j)*4;
                int ng = n0 + nn;
                bool ok = (kg < K) && (ng < N);
                const float* g = (ng < N1) ? &B1[(size_t)kg*ldb1 + ng]
                                           : &B2[(size_t)kg*ldb2 + (ng - N1)];
                uint32_t sa = (uint32_t)__cvta_generic_to_shared(&Bs[kk*136 + nn]);
                cp16(sa, g, ok);
            }
        } else {
            int n = t >> 1, half = t & 1;
            int ng = n0 + n;
            bool okrow = ng < N;
            const float* brow = okrow ? ((ng < N1) ? &B1[(size_t)ng*ldb1]
                                                   : &B2[(size_t)(ng-N1)*ldb2]) : B1;
#pragma unroll
            for (int j = 0; j < 4; j++) {
                int kg = k0 + half*16 + j*4;
                bool ok = okrow && (kg < K);
                uint32_t sa = (uint32_t)__cvta_generic_to_shared(&Bs[n*40 + half*16 + j*4]);
                cp16(sa, &brow[kg], ok);
            }
        }
        asm volatile("cp.async.commit_group;");
    };

    issue(kt0, 0);
    for (int kt = kt0; kt < kt1; kt++) {
        int bufi = (kt - kt0) & 1;
        bool more = (kt + 1 < kt1);
        if (more) issue(kt + 1, bufi ^ 1);
        if (more) asm volatile("cp.async.wait_group 1;");
        else      asm volatile("cp.async.wait_group 0;");
        __syncthreads();
        float* As = smbase + bufi*BUFF;
        mma_tile<BTR>(As, As + 1280, mrow, nq, c0, c1);
        __syncthreads();
    }
    float* cb = part + slab + (size_t)(m0 + mrow*16)*ldp + n0 + nq*32;
    wmma::store_matrix_sync(cb,      c0, ldp, wmma::mem_row_major);
    wmma::store_matrix_sync(cb + 16, c1, ldp, wmma::mem_row_major);
}

template<bool REDA, bool GATEA>
__device__ __forceinline__ void gemm_w(
    const float* __restrict__ A, int M, int K, int lda,
    int Zred, size_t slabA, float ascale, const float* __restrict__ gateA,
    const float* __restrict__ B1, const float* __restrict__ B2,
    int N1, int N, int ldb1, int ldb2,
    float* __restrict__ part, size_t slab, int ldp,
    int m0, int n0, int kt0, int kt1, float* __restrict__ smbase)
{
    const int t = threadIdx.x;
    const int warp = t >> 5, mrow = warp >> 2, nq = warp & 3;
    float* As = smbase;
    float* Bs = smbase + 1280;
    FragC c0, c1;
    wmma::fill_fragment(c0, 0.f);
    wmma::fill_fragment(c1, 0.f);

    for (int kt = kt0; kt < kt1; kt++) {
        int k0 = kt*32;
        {
            int mm = t >> 3, kq = (t & 7)*4;
            int mg = m0 + mm, kg = k0 + kq;
            float4 v = make_float4(0,0,0,0);
            if (mg < M && kg + 3 < K) {
                if (REDA) {
                    for (int z = 0; z < Zred; z++) {
                        float4 w = *(const float4*)&A[(size_t)z*slabA + (size_t)mg*lda + kg];
                        v.x+=w.x; v.y+=w.y; v.z+=w.z; v.w+=w.w;
                    }
                } else v = *(const float4*)&A[(size_t)mg*lda + kg];
                v.x*=ascale; v.y*=ascale; v.z*=ascale; v.w*=ascale;
                if (GATEA) {
                    float4 g = *(const float4*)&gateA[(size_t)mg*lda + kg];
                    v.x*=g.x; v.y*=g.y; v.z*=g.z; v.w*=g.w;
                }
            } else if (mg < M) {
                float tmp[4] = {0,0,0,0};
                for (int j = 0; j < 4; j++) {
                    int k2 = kg + j;
                    if (k2 < K) {
                        float s = 0.f;
                        if (REDA) { for (int z=0; z<Zred; z++) s += A[(size_t)z*slabA + (size_t)mg*lda + k2]; }
                        else s = A[(size_t)mg*lda + k2];
                        s *= ascale;
                        if (GATEA) s *= gateA[(size_t)mg*lda + k2];
                        tmp[j] = s;
                    }
                }
                v = make_float4(tmp[0],tmp[1],tmp[2],tmp[3]);
            }
            *(float4*)&As[ (t>>3)*40 + (t&7)*4 ] = v;
        }
        {
            int kk = t >> 3, cc = t & 7;
            int kg = k0 + kk;
#pragma unroll
            for (int j = 0; j < 4; j++) {
                int nn = (cc + 8*j)*4;
                int ng = n0 + nn;
                float4 v = make_float4(0,0,0,0);
                if (kg < K && ng < N) {
                    if (ng < N1) v = *(const float4*)&B1[(size_t)kg*ldb1 + ng];
                    else         v = *(const float4*)&B2[(size_t)kg*ldb2 + (ng-N1)];
                }
                *(float4*)&Bs[kk*136 + nn] = v;
            }
        }
        __syncthreads();
        mma_tile<false>(As, Bs, mrow, nq, c0, c1);
        __syncthreads();
    }
    float* cb = part + slab + (size_t)(m0 + mrow*16)*ldp + n0 + nq*32;
    wmma::store_matrix_sync(cb,      c0, ldp, wmma::mem_row_major);
    wmma::store_matrix_sync(cb + 16, c1, ldp, wmma::mem_row_major);
}

// stage unit counts
#define U_MLP   40
#define U_QP1   320
#define S0U     (U_MLP+U_QP1)     // 360
#define U_QP2   200
#define U_AVG   256
#define S1U     (U_QP2+U_AVG)     // 456
#define U_QR    160
#define U_GATP  154
#define S2U     (U_QR+U_GATP)     // 314
#define U_GR    166
#define U_QK    440
#define S3U     (U_GR+U_QK)       // 606

__global__ void __launch_bounds__(256, 3) fused_k(
    const float* __restrict__ sc,  const float* __restrict__ bw,
    const float* __restrict__ ss,  const float* __restrict__ bsm,
    const float* __restrict__ qf,
    const float* __restrict__ Wm1, const float* __restrict__ bm1,
    const float* __restrict__ Wm2, const float* __restrict__ bm2,
    const float* __restrict__ Wvis,const float* __restrict__ bvis,
    const float* __restrict__ Wsem,const float* __restrict__ bsem,
    const float* __restrict__ Wq,  const float* __restrict__ Wk,
    const float* __restrict__ Wv,  const float* __restrict__ Wqs,
    const float* __restrict__ Wks, const float* __restrict__ Wfc,
    const float* __restrict__ temp, float* __restrict__ outL)
{
    extern __shared__ __align__(32) float sm[];
    const int NBLK = gridDim.x;
    const int t = threadIdx.x;
    const uint64_t pol = mkpolicy();
    int gen = 1;

    // ===== S0: MLP | qp1 (sc@Wq, pipelined) =====
    for (int u = blockIdx.x; u < S0U; u += NBLK) {
        if (u < U_MLP) {
            int m0u = u * 4;
            for (int i = t; i < 4*SEM; i += 256)
                sm[i] = ss[(size_t)(m0u + i/SEM)*SEM + (i % SEM)];
            __syncthreads();
            for (int n = t; n < SEM; n += 256) {
                float a0 = bm1[n], a1 = a0, a2 = a0, a3 = a0;
                for (int k = 0; k < SEM; k++) {
                    float w = Wm1[(size_t)k*SEM + n];
                    a0 = fmaf(sm[0*SEM+k], w, a0); a1 = fmaf(sm[1*SEM+k], w, a1);
                    a2 = fmaf(sm[2*SEM+k], w, a2); a3 = fmaf(sm[3*SEM+k], w, a3);
                }
                sm[1280 + 0*SEM + n] = (a0 >= 0.f) ? a0 : 0.1f*a0;
                sm[1280 + 1*SEM + n] = (a1 >= 0.f) ? a1 : 0.1f*a1;
                sm[1280 + 2*SEM + n] = (a2 >= 0.f) ? a2 : 0.1f*a2;
                sm[1280 + 3*SEM + n] = (a3 >= 0.f) ? a3 : 0.1f*a3;
            }
            __syncthreads();
            for (int n = t; n < SEM; n += 256) {
                float a0 = bm2[n], a1 = a0, a2 = a0, a3 = a0;
                for (int k = 0; k < SEM; k++) {
                    float w = Wm2[(size_t)k*SEM + n];
                    a0 = fmaf(sm[1280+0*SEM+k], w, a0); a1 = fmaf(sm[1280+1*SEM+k], w, a1);
                    a2 = fmaf(sm[1280+2*SEM+k], w, a2); a3 = fmaf(sm[1280+3*SEM+k], w, a3);
                }
                g_scal[(size_t)(m0u+0)*SEM + n] = a0;
                g_scal[(size_t)(m0u+1)*SEM + n] = a1;
                g_scal[(size_t)(m0u+2)*SEM + n] = a2;
                g_scal[(size_t)(m0u+3)*SEM + n] = a3;
            }
            __syncthreads();
        } else {
            int uu = u - U_MLP;
            int z = uu & 7, r = uu >> 3;
            int nt = r & 7, mt = r >> 3;
            gemm_pipe<false>(sc, BTOT, FD, FD, Wq, Wq, FD, FD, FD, FD,
                g_part, (size_t)z*MNq, FD, mt*32, nt*128, z*4, z*4+4, sm);
        }
    }
    gsync(gen);

    // ===== S1: qp2 (s@Wqs, pipelined) | avg partials (v8 bank read) =====
    for (int u = blockIdx.x; u < S1U; u += NBLK) {
        if (u < U_QP2) {
            int z = u % 5, r = u / 5;
            int nt = r & 7, mt = r >> 3;
            gemm_pipe<false>(g_scal, BTOT, SEM, SEM, Wqs, Wqs, FD, FD, FD, FD,
                g_part, (size_t)(8+z)*MNq, FD, mt*32, nt*128, z*2, z*2+2, sm);
        } else {
            int uu = u - U_QP2;
            int b = uu & 31, rc = uu >> 5;     // 8 row-chunks of 64
            int n0 = rc*64;
            if (t < 128) {
                const float* base = bw + ((size_t)b*NB + n0)*FD + t*8;
                float4 s0 = make_float4(0,0,0,0), s1 = make_float4(0,0,0,0);
#pragma unroll 8
                for (int r = 0; r < 64; r++) {
                    float4 a, bb;
                    ldg_el8(base + (size_t)r*FD, a, bb);
                    s0.x+=a.x; s0.y+=a.y; s0.z+=a.z; s0.w+=a.w;
                    s1.x+=bb.x; s1.y+=bb.y; s1.z+=bb.z; s1.w+=bb.w;
                }
                float* dst = &g_avgp[(size_t)rc*BS*CATD + (size_t)b*CATD + t*8];
                *(float4*)dst = s0;
                *(float4*)(dst+4) = s1;
            } else if (t < 203) {
                int c4 = t - 128;  // 0..74
                const float4* p = (const float4*)(bsm + ((size_t)b*NB + n0)*SEM) + c4;
                float4 s = make_float4(0,0,0,0);
#pragma unroll 8
                for (int r = 0; r < 64; r++) {
                    float4 x = ldg_el(p + (size_t)r*(SEM/4), pol);
                    s.x+=x.x; s.y+=x.y; s.z+=x.z; s.w+=x.w;
                }
                *(float4*)&g_avgp[(size_t)rc*BS*CATD + (size_t)b*CATD + FD + c4*4] = s;
            }
        }
    }
    gsync(gen);

    // ===== S2: q reduce | gates GEMM partials (Zred=8) =====
    for (int u = blockIdx.x; u < S2U; u += NBLK) {
        if (u < U_QR) {
            size_t i4 = (size_t)u*256 + t;
            float4 v = make_float4(0,0,0,0);
#pragma unroll
            for (int z = 0; z < 13; z++) {
                float4 w = ((const float4*)g_part)[(size_t)z*(MNq/4) + i4];
                v.x+=w.x; v.y+=w.y; v.z+=w.z; v.w+=w.w;
            }
            ((float4*)g_q)[i4] = v;
        } else {
            int uu = u - U_QR;
            int z = uu % 14, nt = uu / 14;
            gemm_w<true,false>(g_avgp, BS, CATD, CATD, 8, (size_t)BS*CATD, 1.f/NB, nullptr,
                Wvis, Wsem, FD, CATD, FD, SEM,
                g_part2, (size_t)z*SLABG, 1408, 0, nt*128, z*3, z*3+3, sm);
        }
    }
    gsync(gen);

    // ===== S3: gates reduce | qk GEMM =====
    for (int u = blockIdx.x; u < S3U; u += NBLK) {
        if (u < U_GR) {
            size_t i = (size_t)u*256 + t;
            if (i < (size_t)BS*CATD) {
                int m = (int)(i / CATD), n = (int)(i % CATD);
                float v = 0.f;
#pragma unroll
                for (int z = 0; z < 14; z++) v += g_part2[(size_t)z*SLABG + (size_t)m*1408 + n];
                if (n < FD) {
                    v += bvis[n];
                    g_gv[(size_t)m*FD + n] = 1.f + 1.f/(1.f + __expf(-v));
                } else {
                    v += bsem[n - FD];
                    g_gs[(size_t)m*SEM + (n - FD)] = 1.f + 1.f/(1.f + __expf(-v));
                }
            }
        } else {
            int uu = u - U_GR;
            int z = uu & 7, r = uu >> 3;
            int nt = r % 11, mt = r / 11;
            gemm_pipe<true>(g_q, BTOT, FD, FD, Wk, Wks, FD, CATD, FD, FD,
                g_part, (size_t)z*SLABK, 1408, mt*32, nt*128, z*4, z*4+4, sm);
        }
    }
    gsync(gen);

    // ===== S4: qk reduce * gates =====
    for (int u = blockIdx.x; u < 828; u += NBLK) {
        size_t i = (size_t)u*256 + t;
        if (i < (size_t)MNk) {
            int m = (int)(i / CATD), n = (int)(i % CATD);
            float v = 0.f;
#pragma unroll
            for (int z = 0; z < 8; z++) v += g_part[(size_t)z*SLABK + (size_t)m*1408 + n];
            int b = m / NWAY;
            if (n < FD) g_qkg [(size_t)m*FD  + n]      = v * g_gv[(size_t)b*FD  + n];
            else        g_qksg[(size_t)m*SEM + (n-FD)] = v * g_gs[(size_t)b*SEM + (n-FD)];
        }
    }
    gsync(gen);

    // ===== S5: scores (v8 bank loads on FD part) =====
    for (int u = blockIdx.x; u < 512; u += NBLK) {
        int b = u / 16, ch = u % 16;
        int w = t >> 5, lane = t & 31;
        int nbase = ch*32 + w*4;
        float acc[4][5];
#pragma unroll
        for (int j = 0; j < 4; j++)
#pragma unroll
            for (int p = 0; p < 5; p++) acc[j][p] = 0.f;
        const float4* qkg4 = (const float4*)g_qkg  + (size_t)b*NWAY*(FD/4);
        const float4* qks4 = (const float4*)g_qksg + (size_t)b*NWAY*(SEM/4);
        const float*  bwf  = bw + (size_t)b*NB*FD;
        const float4* bs4  = (const float4*)bsm + (size_t)b*NB*(SEM/4);
#pragma unroll
        for (int tt = 0; tt < 4; tt++) {
            int c8 = tt*32 + lane;           // 8-float chunk (128 chunks over FD)
            float4 xa[4], xb[4];
#pragma unroll
            for (int j = 0; j < 4; j++)
                ldg_el8(bwf + (size_t)(nbase+j)*FD + c8*8, xa[j], xb[j]);
#pragma unroll
            for (int p = 0; p < 5; p++) {
                float4 qa = qkg4[p*(FD/4) + 2*c8];
                float4 qb = qkg4[p*(FD/4) + 2*c8 + 1];
#pragma unroll
                for (int j = 0; j < 4; j++)
                    acc[j][p] += d4(xa[j], qa) + d4(xb[j], qb);
            }
        }
#pragma unroll
        for (int tt = 0; tt < 3; tt++) {
            int c = tt*32 + lane;
            bool ok = c < (SEM/4);
            float4 qv[5];
#pragma unroll
            for (int p = 0; p < 5; p++)
                qv[p] = ok ? qks4[p*(SEM/4) + c] : make_float4(0,0,0,0);
#pragma unroll
            for (int j = 0; j < 4; j++) {
                float4 x = ok ? ldg_el(&bs4[(size_t)(nbase+j)*(SEM/4) + c], pol) : make_float4(0,0,0,0);
#pragma unroll
                for (int p = 0; p < 5; p++) acc[j][p] += d4(x, qv[p]);
            }
        }
#pragma unroll
        for (int off = 16; off; off >>= 1)
#pragma unroll
            for (int j = 0; j < 4; j++)
#pragma unroll
                for (int p = 0; p < 5; p++)
                    acc[j][p] += __shfl_xor_sync(0xffffffffu, acc[j][p], off);
#pragma unroll
        for (int j = 0; j < 4; j++)
            if (lane == j) {
                int n = nbase + j;
#pragma unroll
                for (int p = 0; p < 5; p++)
                    g_scr[(size_t)(b*NWAY+p)*NB + n] = acc[j][p] * (1.f/32.f);
            }
    }
    gsync(gen);

    // ===== S6: fused softmax + nway-avg attention + mix partials (v8 bank) =====
    for (int u = blockIdx.x; u < 512; u += NBLK) {
        int b = u >> 4, chunk = u & 15;
        int n0 = chunk*32;
        int w = t >> 5, lane = t & 31;
        for (int i = t; i < NWAY*NB; i += 256)
            sm[i] = g_scr[(size_t)b*NWAY*NB + i];
        __syncthreads();
        float mx[5];
#pragma unroll
        for (int p = 0; p < 5; p++)
            mx[p] = fmaxf(sm[p*NB + t], sm[p*NB + 256 + t]);
#pragma unroll
        for (int off = 16; off; off >>= 1)
#pragma unroll
            for (int p = 0; p < 5; p++)
                mx[p] = fmaxf(mx[p], __shfl_xor_sync(0xffffffffu, mx[p], off));
        if (lane == 0)
#pragma unroll
            for (int p = 0; p < 5; p++) sm[2624 + w*5 + p] = mx[p];
        __syncthreads();
        if (t < 5) {
            float m = sm[2624 + t];
            for (int w2 = 1; w2 < 8; w2++) m = fmaxf(m, sm[2624 + w2*5 + t]);
            sm[2680 + t] = m;
        }
        __syncthreads();
        float sme[5];
#pragma unroll
        for (int p = 0; p < 5; p++) {
            float m = sm[2680 + p];
            sme[p] = __expf(sm[p*NB + t] - m) + __expf(sm[p*NB + 256 + t] - m);
        }
#pragma unroll
        for (int off = 16; off; off >>= 1)
#pragma unroll
            for (int p = 0; p < 5; p++)
                sme[p] += __shfl_xor_sync(0xffffffffu, sme[p], off);
        if (lane == 0)
#pragma unroll
            for (int p = 0; p < 5; p++) sm[2624 + w*5 + p] = sme[p];
        __syncthreads();
        if (t < 5) {
            float s = 0.f;
            for (int w2 = 0; w2 < 8; w2++) s += sm[2624 + w2*5 + t];
            sm[2688 + t] = 1.f / s;
        }
        __syncthreads();
        if (t < 32) {
            int n = n0 + t;
            float a = 0.f;
#pragma unroll
            for (int p = 0; p < 5; p++)
                a += __expf(sm[p*NB + n] - sm[2680 + p]) * sm[2688 + p];
            sm[2696 + t] = a * (1.f/NWAY);
        }
        __syncthreads();
        if (t < 128) {
            const float* base = bw + ((size_t)b*NB + n0)*FD + t*8;
            float4 s0 = make_float4(0,0,0,0), s1 = make_float4(0,0,0,0);
#pragma unroll 16
            for (int r = 0; r < 32; r++) {
                float4 a, bb;
                ldg_el8(base + (size_t)r*FD, a, bb);
                float wv = sm[2696 + r];
                s0.x = fmaf(a.x, wv, s0.x); s0.y = fmaf(a.y, wv, s0.y);
                s0.z = fmaf(a.z, wv, s0.z); s0.w = fmaf(a.w, wv, s0.w);
                s1.x = fmaf(bb.x, wv, s1.x); s1.y = fmaf(bb.y, wv, s1.y);
                s1.z = fmaf(bb.z, wv, s1.z); s1.w = fmaf(bb.w, wv, s1.w);
            }
            float* dst = &g_mixp[(size_t)chunk*SLABF + (size_t)b*FD + t*8];
            *(float4*)dst = s0;
            *(float4*)(dst+4) = s1;
        }
        __syncthreads();
    }
    gsync(gen);

    // ===== S7: fakev = (mixavg * gv) @ Wv, split-K 32 (256 units) =====
    for (int u = blockIdx.x; u < 256; u += NBLK) {
        int z = u & 31, nt = u >> 5;
        gemm_w<true,true>(g_mixp, BS, FD, FD, 16, (size_t)SLABF, 1.f, g_gv,
            Wv, Wv, FD, FD, FD, FD,
            g_part, (size_t)z*SLABF, FD, 0, nt*128, z, z+1, sm);
    }
    gsync(gen);

    // ===== S8: fakefc = reduce(fakev) @ Wfc, split-K 32 (slabs 32..63) =====
    for (int u = blockIdx.x; u < 256; u += NBLK) {
        int z = u & 31, nt = u >> 5;
        gemm_w<true,false>(g_part, BS, FD, FD, 32, (size_t)SLABF, 1.f, nullptr,
            Wfc, Wfc, FD, FD, FD, FD,
            g_part, (size_t)(32+z)*SLABF, FD, 0, nt*128, z, z+1, sm);
    }
    gsync(gen);

    // ===== S9: fake + norms + logits =====
    for (int u = blockIdx.x; u < BS*10; u += NBLK) {
        int b = u / 10, qc = u % 10;
        {
            const float4* sc4 = (const float4*)sc + (size_t)b*NWAY*(FD/4);
            float4 f = make_float4(0,0,0,0);
            float sq[6];
#pragma unroll
            for (int c = 0; c < NWAY; c++) {
                float4 o = sc4[c*(FD/4) + t];
                sq[c] = d4(o, o);
                f.x+=o.x; f.y+=o.y; f.z+=o.z; f.w+=o.w;
            }
            f.x*=0.2f; f.y*=0.2f; f.z*=0.2f; f.w*=0.2f;
#pragma unroll
            for (int z = 32; z < 64; z++) {
                float4 w2 = ((const float4*)g_part)[(size_t)z*(SLABF/4) + (size_t)b*(FD/4) + t];
                f.x+=w2.x; f.y+=w2.y; f.z+=w2.z; f.w+=w2.w;
            }
            ((float4*)sm)[t] = f;
            sq[5] = d4(f, f);
#pragma unroll
            for (int off = 16; off; off >>= 1)
#pragma unroll
                for (int r = 0; r < 6; r++)
                    sq[r] += __shfl_xor_sync(0xffffffffu, sq[r], off);
            int lane = t & 31, w = t >> 5;
            if (lane == 0)
#pragma unroll
                for (int r = 0; r < 6; r++) sm[1024 + w*6 + r] = sq[r];
            __syncthreads();
            if (t < 6) {
                float s = 0.f;
                for (int w2 = 0; w2 < 8; w2++) s += sm[1024 + w2*6 + t];
                sm[1072 + t] = 1.f / sqrtf(s);
            }
            __syncthreads();
        }
        {
            int w = t >> 5, lane = t & 31;
            int iq = qc*8 + w;
            if (iq < NQ) {
                const float4* q4  = (const float4*)qf + ((size_t)b*NQ + iq)*(FD/4);
                const float4* sc4 = (const float4*)sc + (size_t)b*NWAY*(FD/4);
                const float4* f4  = (const float4*)sm;
                float qq = 0.f, d[6] = {0,0,0,0,0,0};
                for (int i = lane; i < FD/4; i += 32) {
                    float4 x = q4[i];
                    qq += d4(x, x);
#pragma unroll
                    for (int r = 0; r < NWAY; r++) d[r] += d4(x, sc4[r*(FD/4) + i]);
                    d[5] += d4(x, f4[i]);
                }
#pragma unroll
                for (int off = 16; off; off >>= 1) {
                    qq += __shfl_xor_sync(0xffffffffu, qq, off);
#pragma unroll
                    for (int r = 0; r < 6; r++) d[r] += __shfl_xor_sync(0xffffffffu, d[r], off);
                }
                if (lane == 0) {
                    float s = temp[0] / sqrtf(qq);
                    float* o = outL + ((size_t)b*NQ + iq)*6;
#pragma unroll
                    for (int r = 0; r < 6; r++) o[r] = d[r] * s * sm[1072 + r];
                }
            }
        }
        __syncthreads();
    }
}

// ---------------- host ----------------
extern "C" void kernel_launch(void* const* d_in, const int* in_sizes, int n_in,
                              void* d_out, int out_size)
{
    const float* sc   = (const float*)d_in[0];
    const float* bw   = (const float*)d_in[1];
    const float* ss   = (const float*)d_in[2];
    const float* bsm  = (const float*)d_in[3];
    const float* qf   = (const float*)d_in[4];
    const float* Wm1  = (const float*)d_in[5];
    const float* bm1  = (const float*)d_in[6];
    const float* Wm2  = (const float*)d_in[7];
    const float* bm2  = (const float*)d_in[8];
    const float* Wvis = (const float*)d_in[9];
    const float* bvis = (const float*)d_in[10];
    const float* Wsem = (const float*)d_in[11];
    const float* bsem = (const float*)d_in[12];
    const float* Wq   = (const float*)d_in[13];
    const float* Wk   = (const float*)d_in[14];
    const float* Wv   = (const float*)d_in[15];
    const float* Wqs  = (const float*)d_in[16];
    const float* Wks  = (const float*)d_in[17];
    const float* Wfc  = (const float*)d_in[18];
    const float* temp = (const float*)d_in[19];
    float* out = (float*)d_out;

    const int smem_bytes = SMEMF * sizeof(float);  // 51200
    cudaFuncSetAttribute(fused_k, cudaFuncAttributeMaxDynamicSharedMemorySize, smem_bytes);

    int dev = 0;
    cudaGetDevice(&dev);
    int nsm = 148;
    cudaDeviceGetAttribute(&nsm, cudaDevAttrMultiProcessorCount, dev);
    int bpm = 1;
    cudaOccupancyMaxActiveBlocksPerMultiprocessor(&bpm, fused_k, 256, smem_bytes);
    if (bpm < 1) bpm = 1;
    int nblk = nsm * bpm;

    void* barp = nullptr;
    cudaGetSymbolAddress(&barp, g_barrier);
    cudaMemsetAsync(barp, 0, sizeof(unsigned int), 0);

    fused_k<<<nblk, 256, smem_bytes>>>(sc, bw, ss, bsm, qf, Wm1, bm1, Wm2, bm2,
                                       Wvis, bvis, Wsem, bsem, Wq, Wk, Wv, Wqs, Wks, Wfc,
                                       temp, out);
}

// round 15
// speedup vs baseline: 1.0183x; 1.0183x over previous
#include <cuda_runtime.h>
#include <mma.h>
#include <math.h>
#include <cstdint>

using namespace nvcuda;

#define FD    1024
#define SEM   300
#define NWAY  5
#define BS    32
#define NB    512
#define NQ    75
#define BTOT  (BS*NWAY)     // 160
#define CATD  (FD+SEM)      // 1324

#define MNq   (BTOT*FD)     // 163840
#define MNk   (BTOT*CATD)   // 211840
#define SLABK (BTOT*1408)   // padded qk partial slab
#define SLABG (BS*1408)
#define SLABF (BS*FD)       // 32768

#define SMEMF 12800         // dynamic smem floats (2 x 6400 gemm buffers)
#define BUFF  6400

// ---------------- scratch ----------------
__device__ __align__(32) float g_scal[BTOT*SEM];
__device__ __align__(32) float g_gv  [BS*FD];
__device__ __align__(32) float g_gs  [BS*SEM];
__device__ __align__(32) float g_q   [BTOT*FD];
__device__ __align__(32) float g_qkg [BTOT*FD];
__device__ __align__(32) float g_qksg[BTOT*SEM];
__device__ __align__(32) float g_scr [BTOT*NB];
__device__ __align__(32) float g_avgp[4*BS*CATD];
__device__ __align__(32) float g_mixp[16*SLABF];
__device__ __align__(32) float g_part [16*MNq];
__device__ __align__(32) float g_part2[14*SLABG];
__device__ unsigned int g_barrier;

// ---------------- software grid barrier ----------------
__device__ __forceinline__ void gsync(int &gen)
{
    __syncthreads();
    if (threadIdx.x == 0) {
        __threadfence();
        atomicAdd(&g_barrier, 1u);
        unsigned target = (unsigned)gridDim.x * (unsigned)gen;
        unsigned v;
        do {
            asm volatile("ld.acquire.gpu.u32 %0, [%1];" : "=r"(v) : "l"(&g_barrier) : "memory");
            if (v >= target) break;
            __nanosleep(32);
        } while (true);
    }
    __syncthreads();
    gen++;
}

__device__ __forceinline__ float d4(float4 a, float4 b)
{ return a.x*b.x + a.y*b.y + a.z*b.z + a.w*b.w; }

__device__ __forceinline__ uint64_t mkpolicy()
{
    uint64_t p;
    asm volatile("createpolicy.fractional.L2::evict_last.b64 %0, 1.0;" : "=l"(p));
    return p;
}

__device__ __forceinline__ float4 ldg_el(const float4* p, uint64_t pol)
{
    float4 v;
    asm volatile("ld.global.L2::cache_hint.v4.f32 {%0,%1,%2,%3}, [%4], %5;"
        : "=f"(v.x), "=f"(v.y), "=f"(v.z), "=f"(v.w) : "l"(p), "l"(pol));
    return v;
}

__device__ __forceinline__ void cp16(uint32_t saddr, const void* g, bool pred)
{
    asm volatile("cp.async.ca.shared.global [%0], [%1], 16, %2;"
        :: "r"(saddr), "l"(g), "r"(pred ? 16 : 0));
}

typedef wmma::fragment<wmma::matrix_a, 16,16,8, wmma::precision::tf32, wmma::row_major> FragA;
typedef wmma::fragment<wmma::matrix_b, 16,16,8, wmma::precision::tf32, wmma::row_major> FragBR;
typedef wmma::fragment<wmma::matrix_b, 16,16,8, wmma::precision::tf32, wmma::col_major> FragBC;
typedef wmma::fragment<wmma::accumulator, 16,16,8, float> FragC;

template<class F>
__device__ __forceinline__ void split_frag(F& hi, F& lo)
{
#pragma unroll
    for (int i = 0; i < hi.num_elements; i++) {
        float r = hi.x[i];
        float h = wmma::__float_to_tf32(r);
        hi.x[i] = h;
        lo.x[i] = wmma::__float_to_tf32(r - h);
    }
}

template<bool BTR>
__device__ __forceinline__ void mma_tile(float* As, float* Bs, int mrow, int nq,
                                         FragC& c0, FragC& c1)
{
#pragma unroll
    for (int kk = 0; kk < 32; kk += 8) {
        FragA ah, al;
        wmma::load_matrix_sync(ah, As + mrow*16*40 + kk, 40);
        split_frag(ah, al);
        if (!BTR) {
            FragBR b0h,b0l,b1h,b1l;
            wmma::load_matrix_sync(b0h, Bs + kk*136 + nq*32, 136);
            wmma::load_matrix_sync(b1h, Bs + kk*136 + nq*32 + 16, 136);
            split_frag(b0h, b0l); split_frag(b1h, b1l);
            wmma::mma_sync(c0, ah, b0h, c0);
            wmma::mma_sync(c0, ah, b0l, c0);
            wmma::mma_sync(c0, al, b0h, c0);
            wmma::mma_sync(c1, ah, b1h, c1);
            wmma::mma_sync(c1, ah, b1l, c1);
            wmma::mma_sync(c1, al, b1h, c1);
        } else {
            FragBC b0h,b0l,b1h,b1l;
            wmma::load_matrix_sync(b0h, Bs + (nq*32)*40 + kk, 40);
            wmma::load_matrix_sync(b1h, Bs + (nq*32+16)*40 + kk, 40);
            split_frag(b0h, b0l); split_frag(b1h, b1l);
            wmma::mma_sync(c0, ah, b0h, c0);
            wmma::mma_sync(c0, ah, b0l, c0);
            wmma::mma_sync(c0, al, b0h, c0);
            wmma::mma_sync(c1, ah, b1h, c1);
            wmma::mma_sync(c1, ah, b1l, c1);
            wmma::mma_sync(c1, al, b1h, c1);
        }
    }
}

template<bool BTR>
__device__ __forceinline__ void gemm_pipe(
    const float* __restrict__ A, int M, int K, int lda,
    const float* __restrict__ B1, const float* __restrict__ B2,
    int N1, int N, int ldb1, int ldb2,
    float* __restrict__ part, size_t slab, int ldp,
    int m0, int n0, int kt0, int kt1, float* __restrict__ smbase)
{
    const int t = threadIdx.x;
    const int warp = t >> 5, mrow = warp >> 2, nq = warp & 3;
    FragC c0, c1;
    wmma::fill_fragment(c0, 0.f);
    wmma::fill_fragment(c1, 0.f);

    auto issue = [&](int kt, int bufi) {
        float* As = smbase + bufi*BUFF;
        float* Bs = As + 1280;
        int k0 = kt*32;
        {
            int mm = t >> 3, kq = t & 7;
            int mg = m0 + mm, kg = k0 + kq*4;
            bool ok = (mg < M) && (kg < K);
            uint32_t sa = (uint32_t)__cvta_generic_to_shared(&As[mm*40 + kq*4]);
            cp16(sa, &A[(size_t)mg*lda + kg], ok);
        }
        if (!BTR) {
            int kk = t >> 3, cc = t & 7;
            int kg = k0 + kk;
#pragma unroll
            for (int j = 0; j < 4; j++) {
                int nn = (cc + 8*j)*4;
                int ng = n0 + nn;
                bool ok = (kg < K) && (ng < N);
                const float* g = (ng < N1) ? &B1[(size_t)kg*ldb1 + ng]
                                           : &B2[(size_t)kg*ldb2 + (ng - N1)];
                uint32_t sa = (uint32_t)__cvta_generic_to_shared(&Bs[kk*136 + nn]);
                cp16(sa, g, ok);
            }
        } else {
            int n = t >> 1, half = t & 1;
            int ng = n0 + n;
            bool okrow = ng < N;
            const float* brow = okrow ? ((ng < N1) ? &B1[(size_t)ng*ldb1]
                                                   : &B2[(size_t)(ng-N1)*ldb2]) : B1;
#pragma unroll
            for (int j = 0; j < 4; j++) {
                int kg = k0 + half*16 + j*4;
                bool ok = okrow && (kg < K);
                uint32_t sa = (uint32_t)__cvta_generic_to_shared(&Bs[n*40 + half*16 + j*4]);
                cp16(sa, &brow[kg], ok);
            }
        }
        asm volatile("cp.async.commit_group;");
    };

    issue(kt0, 0);
    for (int kt = kt0; kt < kt1; kt++) {
        int bufi = (kt - kt0) & 1;
        bool more = (kt + 1 < kt1);
        if (more) issue(kt + 1, bufi ^ 1);
        if (more) asm volatile("cp.async.wait_group 1;");
        else      asm volatile("cp.async.wait_group 0;");
        __syncthreads();
        float* As = smbase + bufi*BUFF;
        mma_tile<BTR>(As, As + 1280, mrow, nq, c0, c1);
        __syncthreads();
    }
    float* cb = part + slab + (size_t)(m0 + mrow*16)*ldp + n0 + nq*32;
    wmma::store_matrix_sync(cb,      c0, ldp, wmma::mem_row_major);
    wmma::store_matrix_sync(cb + 16, c1, ldp, wmma::mem_row_major);
}

template<bool REDA, bool GATEA>
__device__ __forceinline__ void gemm_w(
    const float* __restrict__ A, int M, int K, int lda,
    int Zred, size_t slabA, float ascale, const float* __restrict__ gateA,
    const float* __restrict__ B1, const float* __restrict__ B2,
    int N1, int N, int ldb1, int ldb2,
    float* __restrict__ part, size_t slab, int ldp,
    int m0, int n0, int kt0, int kt1, float* __restrict__ smbase)
{
    const int t = threadIdx.x;
    const int warp = t >> 5, mrow = warp >> 2, nq = warp & 3;
    float* As = smbase;
    float* Bs = smbase + 1280;
    FragC c0, c1;
    wmma::fill_fragment(c0, 0.f);
    wmma::fill_fragment(c1, 0.f);

    for (int kt = kt0; kt < kt1; kt++) {
        int k0 = kt*32;
        {
            int mm = t >> 3, kq = (t & 7)*4;
            int mg = m0 + mm, kg = k0 + kq;
            float4 v = make_float4(0,0,0,0);
            if (mg < M && kg + 3 < K) {
                if (REDA) {
                    for (int z = 0; z < Zred; z++) {
                        float4 w = *(const float4*)&A[(size_t)z*slabA + (size_t)mg*lda + kg];
                        v.x+=w.x; v.y+=w.y; v.z+=w.z; v.w+=w.w;
                    }
                } else v = *(const float4*)&A[(size_t)mg*lda + kg];
                v.x*=ascale; v.y*=ascale; v.z*=ascale; v.w*=ascale;
                if (GATEA) {
                    float4 g = *(const float4*)&gateA[(size_t)mg*lda + kg];
                    v.x*=g.x; v.y*=g.y; v.z*=g.z; v.w*=g.w;
                }
            } else if (mg < M) {
                float tmp[4] = {0,0,0,0};
                for (int j = 0; j < 4; j++) {
                    int k2 = kg + j;
                    if (k2 < K) {
                        float s = 0.f;
                        if (REDA) { for (int z=0; z<Zred; z++) s += A[(size_t)z*slabA + (size_t)mg*lda + k2]; }
                        else s = A[(size_t)mg*lda + k2];
                        s *= ascale;
                        if (GATEA) s *= gateA[(size_t)mg*lda + k2];
                        tmp[j] = s;
                    }
                }
                v = make_float4(tmp[0],tmp[1],tmp[2],tmp[3]);
            }
            *(float4*)&As[ (t>>3)*40 + (t&7)*4 ] = v;
        }
        {
            int kk = t >> 3, cc = t & 7;
            int kg = k0 + kk;
#pragma unroll
            for (int j = 0; j < 4; j++) {
                int nn = (cc + 8*j)*4;
                int ng = n0 + nn;
                float4 v = make_float4(0,0,0,0);
                if (kg < K && ng < N) {
                    if (ng < N1) v = *(const float4*)&B1[(size_t)kg*ldb1 + ng];
                    else         v = *(const float4*)&B2[(size_t)kg*ldb2 + (ng-N1)];
                }
                *(float4*)&Bs[kk*136 + nn] = v;
            }
        }
        __syncthreads();
        mma_tile<false>(As, Bs, mrow, nq, c0, c1);
        __syncthreads();
    }
    float* cb = part + slab + (size_t)(m0 + mrow*16)*ldp + n0 + nq*32;
    wmma::store_matrix_sync(cb,      c0, ldp, wmma::mem_row_major);
    wmma::store_matrix_sync(cb + 16, c1, ldp, wmma::mem_row_major);
}

// stage unit counts
#define U_MLP   40
#define U_QP1   320
#define S0U     (U_MLP+U_QP1)     // 360
#define U_QP2   200
#define U_AVG   256
#define S1U     (U_QP2+U_AVG)     // 456
#define U_QR    160
#define U_GATP  154
#define S2U     (U_QR+U_GATP)     // 314
#define U_GR    166
#define U_QK    440
#define S3U     (U_GR+U_QK)       // 606

__global__ void __launch_bounds__(256, 3) fused_k(
    const float* __restrict__ sc,  const float* __restrict__ bw,
    const float* __restrict__ ss,  const float* __restrict__ bsm,
    const float* __restrict__ qf,
    const float* __restrict__ Wm1, const float* __restrict__ bm1,
    const float* __restrict__ Wm2, const float* __restrict__ bm2,
    const float* __restrict__ Wvis,const float* __restrict__ bvis,
    const float* __restrict__ Wsem,const float* __restrict__ bsem,
    const float* __restrict__ Wq,  const float* __restrict__ Wk,
    const float* __restrict__ Wv,  const float* __restrict__ Wqs,
    const float* __restrict__ Wks, const float* __restrict__ Wfc,
    const float* __restrict__ temp, float* __restrict__ outL)
{
    extern __shared__ __align__(32) float sm[];
    const int NBLK = gridDim.x;
    const int t = threadIdx.x;
    const uint64_t pol = mkpolicy();
    int gen = 1;

    // ===== S0: MLP | qp1 (sc@Wq, pipelined) =====
    for (int u = blockIdx.x; u < S0U; u += NBLK) {
        if (u < U_MLP) {
            int m0u = u * 4;
            for (int i = t; i < 4*SEM; i += 256)
                sm[i] = ss[(size_t)(m0u + i/SEM)*SEM + (i % SEM)];
            __syncthreads();
            for (int n = t; n < SEM; n += 256) {
                float a0 = bm1[n], a1 = a0, a2 = a0, a3 = a0;
                for (int k = 0; k < SEM; k++) {
                    float w = Wm1[(size_t)k*SEM + n];
                    a0 = fmaf(sm[0*SEM+k], w, a0); a1 = fmaf(sm[1*SEM+k], w, a1);
                    a2 = fmaf(sm[2*SEM+k], w, a2); a3 = fmaf(sm[3*SEM+k], w, a3);
                }
                sm[1280 + 0*SEM + n] = (a0 >= 0.f) ? a0 : 0.1f*a0;
                sm[1280 + 1*SEM + n] = (a1 >= 0.f) ? a1 : 0.1f*a1;
                sm[1280 + 2*SEM + n] = (a2 >= 0.f) ? a2 : 0.1f*a2;
                sm[1280 + 3*SEM + n] = (a3 >= 0.f) ? a3 : 0.1f*a3;
            }
            __syncthreads();
            for (int n = t; n < SEM; n += 256) {
                float a0 = bm2[n], a1 = a0, a2 = a0, a3 = a0;
                for (int k = 0; k < SEM; k++) {
                    float w = Wm2[(size_t)k*SEM + n];
                    a0 = fmaf(sm[1280+0*SEM+k], w, a0); a1 = fmaf(sm[1280+1*SEM+k], w, a1);
                    a2 = fmaf(sm[1280+2*SEM+k], w, a2); a3 = fmaf(sm[1280+3*SEM+k], w, a3);
                }
                g_scal[(size_t)(m0u+0)*SEM + n] = a0;
                g_scal[(size_t)(m0u+1)*SEM + n] = a1;
                g_scal[(size_t)(m0u+2)*SEM + n] = a2;
                g_scal[(size_t)(m0u+3)*SEM + n] = a3;
            }
            __syncthreads();
        } else {
            int uu = u - U_MLP;
            int z = uu & 7, r = uu >> 3;
            int nt = r & 7, mt = r >> 3;
            gemm_pipe<false>(sc, BTOT, FD, FD, Wq, Wq, FD, FD, FD, FD,
                g_part, (size_t)z*MNq, FD, mt*32, nt*128, z*4, z*4+4, sm);
        }
    }
    gsync(gen);

    // ===== S1: qp2 (s@Wqs, pipelined) | avg partials (evict_last) =====
    for (int u = blockIdx.x; u < S1U; u += NBLK) {
        if (u < U_QP2) {
            int z = u % 5, r = u / 5;
            int nt = r & 7, mt = r >> 3;
            gemm_pipe<false>(g_scal, BTOT, SEM, SEM, Wqs, Wqs, FD, FD, FD, FD,
                g_part, (size_t)(8+z)*MNq, FD, mt*32, nt*128, z*2, z*2+2, sm);
        } else {
            int uu = u - U_QP2;
            int chunk = uu >> 6, r = uu & 63;
            int b = r >> 1, cpart = r & 1;
            int c4 = cpart*256 + t;
            if (c4 < CATD/4) {
                int c = c4*4;
                int n0 = chunk*128;
                float4 v = make_float4(0,0,0,0);
                if (c < FD) {
                    const float4* p = (const float4*)bw + ((size_t)b*NB + n0)*(FD/4) + c4;
#pragma unroll 16
                    for (int n = 0; n < 128; n++) {
                        float4 x = ldg_el(&p[(size_t)n*(FD/4)], pol);
                        v.x+=x.x; v.y+=x.y; v.z+=x.z; v.w+=x.w;
                    }
                } else {
                    const float4* p = (const float4*)(bsm + ((size_t)b*NB + n0)*SEM + (c-FD));
#pragma unroll 16
                    for (int n = 0; n < 128; n++) {
                        float4 x = ldg_el(&p[(size_t)n*(SEM/4)], pol);
                        v.x+=x.x; v.y+=x.y; v.z+=x.z; v.w+=x.w;
                    }
                }
                *(float4*)&g_avgp[(size_t)chunk*BS*CATD + (size_t)b*CATD + c] = v;
            }
        }
    }
    gsync(gen);

    // ===== S2: q reduce | gates GEMM partials =====
    for (int u = blockIdx.x; u < S2U; u += NBLK) {
        if (u < U_QR) {
            size_t i4 = (size_t)u*256 + t;
            float4 v = make_float4(0,0,0,0);
#pragma unroll
            for (int z = 0; z < 13; z++) {
                float4 w = ((const float4*)g_part)[(size_t)z*(MNq/4) + i4];
                v.x+=w.x; v.y+=w.y; v.z+=w.z; v.w+=w.w;
            }
            ((float4*)g_q)[i4] = v;
        } else {
            int uu = u - U_QR;
            int z = uu % 14, nt = uu / 14;
            gemm_w<true,false>(g_avgp, BS, CATD, CATD, 4, (size_t)BS*CATD, 1.f/NB, nullptr,
                Wvis, Wsem, FD, CATD, FD, SEM,
                g_part2, (size_t)z*SLABG, 1408, 0, nt*128, z*3, z*3+3, sm);
        }
    }
    gsync(gen);

    // ===== S3: gates reduce | qk GEMM =====
    for (int u = blockIdx.x; u < S3U; u += NBLK) {
        if (u < U_GR) {
            size_t i = (size_t)u*256 + t;
            if (i < (size_t)BS*CATD) {
                int m = (int)(i / CATD), n = (int)(i % CATD);
                float v = 0.f;
#pragma unroll
                for (int z = 0; z < 14; z++) v += g_part2[(size_t)z*SLABG + (size_t)m*1408 + n];
                if (n < FD) {
                    v += bvis[n];
                    g_gv[(size_t)m*FD + n] = 1.f + 1.f/(1.f + __expf(-v));
                } else {
                    v += bsem[n - FD];
                    g_gs[(size_t)m*SEM + (n - FD)] = 1.f + 1.f/(1.f + __expf(-v));
                }
            }
        } else {
            int uu = u - U_GR;
            int z = uu & 7, r = uu >> 3;
            int nt = r % 11, mt = r / 11;
            gemm_pipe<true>(g_q, BTOT, FD, FD, Wk, Wks, FD, CATD, FD, FD,
                g_part, (size_t)z*SLABK, 1408, mt*32, nt*128, z*4, z*4+4, sm);
        }
    }
    gsync(gen);

    // ===== S4: qk reduce * gates =====
    for (int u = blockIdx.x; u < 828; u += NBLK) {
        size_t i = (size_t)u*256 + t;
        if (i < (size_t)MNk) {
            int m = (int)(i / CATD), n = (int)(i % CATD);
            float v = 0.f;
#pragma unroll
            for (int z = 0; z < 8; z++) v += g_part[(size_t)z*SLABK + (size_t)m*1408 + n];
            int b = m / NWAY;
            if (n < FD) g_qkg [(size_t)m*FD  + n]      = v * g_gv[(size_t)b*FD  + n];
            else        g_qksg[(size_t)m*SEM + (n-FD)] = v * g_gs[(size_t)b*SEM + (n-FD)];
        }
    }
    gsync(gen);

    // ===== S5: scores (4 rows per warp, software-pipelined bank loads) =====
    for (int u = blockIdx.x; u < 512; u += NBLK) {
        int b = u / 16, ch = u % 16;
        int w = t >> 5, lane = t & 31;
        int nbase = ch*32 + w*4;
        float acc[4][5];
#pragma unroll
        for (int j = 0; j < 4; j++)
#pragma unroll
            for (int p = 0; p < 5; p++) acc[j][p] = 0.f;
        const float4* qkg4 = (const float4*)g_qkg  + (size_t)b*NWAY*(FD/4);
        const float4* qks4 = (const float4*)g_qksg + (size_t)b*NWAY*(SEM/4);
        const float4* bw4  = (const float4*)bw     + (size_t)b*NB*(FD/4);
        const float4* bs4  = (const float4*)bsm    + (size_t)b*NB*(SEM/4);

        float4 xa[4], xb[4];
#pragma unroll
        for (int j = 0; j < 4; j++)
            xa[j] = ldg_el(&bw4[(size_t)(nbase+j)*(FD/4) + lane], pol);
#pragma unroll
        for (int tt = 0; tt < 8; tt++) {
            int c = tt*32 + lane;
            // prefetch next tile while computing this one
            if (tt < 7) {
                int cn = c + 32;
#pragma unroll
                for (int j = 0; j < 4; j++)
                    xb[j] = ldg_el(&bw4[(size_t)(nbase+j)*(FD/4) + cn], pol);
            }
            float4 qv[5];
#pragma unroll
            for (int p = 0; p < 5; p++) qv[p] = qkg4[p*(FD/4) + c];
#pragma unroll
            for (int j = 0; j < 4; j++)
#pragma unroll
                for (int p = 0; p < 5; p++) acc[j][p] += d4(xa[j], qv[p]);
#pragma unroll
            for (int j = 0; j < 4; j++) xa[j] = xb[j];
        }
#pragma unroll
        for (int tt = 0; tt < 3; tt++) {
            int c = tt*32 + lane;
            bool ok = c < (SEM/4);
            float4 qv[5];
#pragma unroll
            for (int p = 0; p < 5; p++)
                qv[p] = ok ? qks4[p*(SEM/4) + c] : make_float4(0,0,0,0);
#pragma unroll
            for (int j = 0; j < 4; j++) {
                float4 x = ok ? ldg_el(&bs4[(size_t)(nbase+j)*(SEM/4) + c], pol) : make_float4(0,0,0,0);
#pragma unroll
                for (int p = 0; p < 5; p++) acc[j][p] += d4(x, qv[p]);
            }
        }
#pragma unroll
        for (int off = 16; off; off >>= 1)
#pragma unroll
            for (int j = 0; j < 4; j++)
#pragma unroll
                for (int p = 0; p < 5; p++)
                    acc[j][p] += __shfl_xor_sync(0xffffffffu, acc[j][p], off);
#pragma unroll
        for (int j = 0; j < 4; j++)
            if (lane == j) {
                int n = nbase + j;
#pragma unroll
                for (int p = 0; p < 5; p++)
                    g_scr[(size_t)(b*NWAY+p)*NB + n] = acc[j][p] * (1.f/32.f);
            }
    }
    gsync(gen);

    // ===== S6: fused softmax + nway-avg attention + mix partials (512 units) =====
    for (int u = blockIdx.x; u < 512; u += NBLK) {
        int b = u >> 4, chunk = u & 15;
        int n0 = chunk*32;
        int w = t >> 5, lane = t & 31;
        for (int i = t; i < NWAY*NB; i += 256)
            sm[i] = g_scr[(size_t)b*NWAY*NB + i];
        __syncthreads();
        float mx[5];
#pragma unroll
        for (int p = 0; p < 5; p++)
            mx[p] = fmaxf(sm[p*NB + t], sm[p*NB + 256 + t]);
#pragma unroll
        for (int off = 16; off; off >>= 1)
#pragma unroll
            for (int p = 0; p < 5; p++)
                mx[p] = fmaxf(mx[p], __shfl_xor_sync(0xffffffffu, mx[p], off));
        if (lane == 0)
#pragma unroll
            for (int p = 0; p < 5; p++) sm[2624 + w*5 + p] = mx[p];
        __syncthreads();
        if (t < 5) {
            float m = sm[2624 + t];
            for (int w2 = 1; w2 < 8; w2++) m = fmaxf(m, sm[2624 + w2*5 + t]);
            sm[2680 + t] = m;
        }
        __syncthreads();
        float sme[5];
#pragma unroll
        for (int p = 0; p < 5; p++) {
            float m = sm[2680 + p];
            sme[p] = __expf(sm[p*NB + t] - m) + __expf(sm[p*NB + 256 + t] - m);
        }
#pragma unroll
        for (int off = 16; off; off >>= 1)
#pragma unroll
            for (int p = 0; p < 5; p++)
                sme[p] += __shfl_xor_sync(0xffffffffu, sme[p], off);
        if (lane == 0)
#pragma unroll
            for (int p = 0; p < 5; p++) sm[2624 + w*5 + p] = sme[p];
        __syncthreads();
        if (t < 5) {
            float s = 0.f;
            for (int w2 = 0; w2 < 8; w2++) s += sm[2624 + w2*5 + t];
            sm[2688 + t] = 1.f / s;
        }
        __syncthreads();
        if (t < 32) {
            int n = n0 + t;
            float a = 0.f;
#pragma unroll
            for (int p = 0; p < 5; p++)
                a += __expf(sm[p*NB + n] - sm[2680 + p]) * sm[2688 + p];
            sm[2696 + t] = a * (1.f/NWAY);
        }
        __syncthreads();
        float4 acc = make_float4(0,0,0,0);
        const float4* p4 = (const float4*)bw + ((size_t)b*NB + n0)*(FD/4) + t;
#pragma unroll 16
        for (int r = 0; r < 32; r++) {
            float4 x = p4[(size_t)r*(FD/4)];
            float a = sm[2696 + r];
            acc.x = fmaf(x.x, a, acc.x); acc.y = fmaf(x.y, a, acc.y);
            acc.z = fmaf(x.z, a, acc.z); acc.w = fmaf(x.w, a, acc.w);
        }
        ((float4*)g_mixp)[(size_t)chunk*(SLABF/4) + (size_t)b*(FD/4) + t] = acc;
        __syncthreads();
    }
    gsync(gen);

    // ===== S7: fakev = (mixavg * gv) @ Wv, split-K 32 (256 units) =====
    for (int u = blockIdx.x; u < 256; u += NBLK) {
        int z = u & 31, nt = u >> 5;
        gemm_w<true,true>(g_mixp, BS, FD, FD, 16, (size_t)SLABF, 1.f, g_gv,
            Wv, Wv, FD, FD, FD, FD,
            g_part, (size_t)z*SLABF, FD, 0, nt*128, z, z+1, sm);
    }
    gsync(gen);

    // ===== S8: fakefc = reduce(fakev) @ Wfc, split-K 32 (slabs 32..63) =====
    for (int u = blockIdx.x; u < 256; u += NBLK) {
        int z = u & 31, nt = u >> 5;
        gemm_w<true,false>(g_part, BS, FD, FD, 32, (size_t)SLABF, 1.f, nullptr,
            Wfc, Wfc, FD, FD, FD, FD,
            g_part, (size_t)(32+z)*SLABF, FD, 0, nt*128, z, z+1, sm);
    }
    gsync(gen);

    // ===== S9: fake + norms + logits =====
    for (int u = blockIdx.x; u < BS*10; u += NBLK) {
        int b = u / 10, qc = u % 10;
        {
            const float4* sc4 = (const float4*)sc + (size_t)b*NWAY*(FD/4);
            float4 f = make_float4(0,0,0,0);
            float sq[6];
#pragma unroll
            for (int c = 0; c < NWAY; c++) {
                float4 o = sc4[c*(FD/4) + t];
                sq[c] = d4(o, o);
                f.x+=o.x; f.y+=o.y; f.z+=o.z; f.w+=o.w;
            }
            f.x*=0.2f; f.y*=0.2f; f.z*=0.2f; f.w*=0.2f;
#pragma unroll
            for (int z = 32; z < 64; z++) {
                float4 w2 = ((const float4*)g_part)[(size_t)z*(SLABF/4) + (size_t)b*(FD/4) + t];
                f.x+=w2.x; f.y+=w2.y; f.z+=w2.z; f.w+=w2.w;
            }
            ((float4*)sm)[t] = f;
            sq[5] = d4(f, f);
#pragma unroll
            for (int off = 16; off; off >>= 1)
#pragma unroll
                for (int r = 0; r < 6; r++)
                    sq[r] += __shfl_xor_sync(0xffffffffu, sq[r], off);
            int lane = t & 31, w = t >> 5;
            if (lane == 0)
#pragma unroll
                for (int r = 0; r < 6; r++) sm[1024 + w*6 + r] = sq[r];
            __syncthreads();
            if (t < 6) {
                float s = 0.f;
                for (int w2 = 0; w2 < 8; w2++) s += sm[1024 + w2*6 + t];
                sm[1072 + t] = 1.f / sqrtf(s);
            }
            __syncthreads();
        }
        {
            int w = t >> 5, lane = t & 31;
            int iq = qc*8 + w;
            if (iq < NQ) {
                const float4* q4  = (const float4*)qf + ((size_t)b*NQ + iq)*(FD/4);
                const float4* sc4 = (const float4*)sc + (size_t)b*NWAY*(FD/4);
                const float4* f4  = (const float4*)sm;
                float qq = 0.f, d[6] = {0,0,0,0,0,0};
                for (int i = lane; i < FD/4; i += 32) {
                    float4 x = q4[i];
                    qq += d4(x, x);
#pragma unroll
                    for (int r = 0; r < NWAY; r++) d[r] += d4(x, sc4[r*(FD/4) + i]);
                    d[5] += d4(x, f4[i]);
                }
#pragma unroll
                for (int off = 16; off; off >>= 1) {
                    qq += __shfl_xor_sync(0xffffffffu, qq, off);
#pragma unroll
                    for (int r = 0; r < 6; r++) d[r] += __shfl_xor_sync(0xffffffffu, d[r], off);
                }
                if (lane == 0) {
                    float s = temp[0] / sqrtf(qq);
                    float* o = outL + ((size_t)b*NQ + iq)*6;
#pragma unroll
                    for (int r = 0; r < 6; r++) o[r] = d[r] * s * sm[1072 + r];
                }
            }
        }
        __syncthreads();
    }
}

// ---------------- host ----------------
extern "C" void kernel_launch(void* const* d_in, const int* in_sizes, int n_in,
                              void* d_out, int out_size)
{
    const float* sc   = (const float*)d_in[0];
    const float* bw   = (const float*)d_in[1];
    const float* ss   = (const float*)d_in[2];
    const float* bsm  = (const float*)d_in[3];
    const float* qf   = (const float*)d_in[4];
    const float* Wm1  = (const float*)d_in[5];
    const float* bm1  = (const float*)d_in[6];
    const float* Wm2  = (const float*)d_in[7];
    const float* bm2  = (const float*)d_in[8];
    const float* Wvis = (const float*)d_in[9];
    const float* bvis = (const float*)d_in[10];
    const float* Wsem = (const float*)d_in[11];
    const float* bsem = (const float*)d_in[12];
    const float* Wq   = (const float*)d_in[13];
    const float* Wk   = (const float*)d_in[14];
    const float* Wv   = (const float*)d_in[15];
    const float* Wqs  = (const float*)d_in[16];
    const float* Wks  = (const float*)d_in[17];
    const float* Wfc  = (const float*)d_in[18];
    const float* temp = (const float*)d_in[19];
    float* out = (float*)d_out;

    const int smem_bytes = SMEMF * sizeof(float);  // 51200
    cudaFuncSetAttribute(fused_k, cudaFuncAttributeMaxDynamicSharedMemorySize, smem_bytes);

    int dev = 0;
    cudaGetDevice(&dev);
    int nsm = 148;
    cudaDeviceGetAttribute(&nsm, cudaDevAttrMultiProcessorCount, dev);
    int bpm = 1;
    cudaOccupancyMaxActiveBlocksPerMultiprocessor(&bpm, fused_k, 256, smem_bytes);
    if (bpm < 1) bpm = 1;
    int nblk = nsm * bpm;

    void* barp = nullptr;
    cudaGetSymbolAddress(&barp, g_barrier);
    cudaMemsetAsync(barp, 0, sizeof(unsigned int), 0);

    fused_k<<<nblk, 256, smem_bytes>>>(sc, bw, ss, bsm, qf, Wm1, bm1, Wm2, bm2,
                                       Wvis, bvis, Wsem, bsem, Wq, Wk, Wv, Wqs, Wks, Wfc,
                                       temp, out);
}

// round 16
// speedup vs baseline: 1.0578x; 1.0388x over previous
#include <cuda_runtime.h>
#include <mma.h>
#include <math.h>
#include <cstdint>

using namespace nvcuda;

#define FD    1024
#define SEM   300
#define NWAY  5
#define BS    32
#define NB    512
#define NQ    75
#define BTOT  (BS*NWAY)     // 160
#define CATD  (FD+SEM)      // 1324

#define MNq   (BTOT*FD)     // 163840
#define MNk   (BTOT*CATD)   // 211840
#define SLABK (BTOT*1408)   // padded qk partial slab
#define SLABG (BS*1408)
#define SLABF (BS*FD)       // 32768

#define SMEMF 12800         // dynamic smem floats (2 x 6400 gemm buffers)
#define BUFF  6400

// ---------------- scratch ----------------
__device__ __align__(32) float g_scal[BTOT*SEM];
__device__ __align__(32) float g_gv  [BS*FD];
__device__ __align__(32) float g_gs  [BS*SEM];
__device__ __align__(32) float g_q   [BTOT*FD];
__device__ __align__(32) float g_qkg [BTOT*FD];
__device__ __align__(32) float g_qksg[BTOT*SEM];
__device__ __align__(32) float g_scr [BTOT*NB];
__device__ __align__(32) float g_avgp[4*BS*CATD];
__device__ __align__(32) float g_mixp[16*SLABF];
__device__ __align__(32) float g_part [16*MNq];
__device__ __align__(32) float g_part2[14*SLABG];
__device__ unsigned int g_barrier;

// ---------------- software grid barrier ----------------
__device__ __forceinline__ void gsync(int &gen)
{
    __syncthreads();
    if (threadIdx.x == 0) {
        __threadfence();
        atomicAdd(&g_barrier, 1u);
        unsigned target = (unsigned)gridDim.x * (unsigned)gen;
        unsigned v;
        do {
            asm volatile("ld.acquire.gpu.u32 %0, [%1];" : "=r"(v) : "l"(&g_barrier) : "memory");
            if (v >= target) break;
            __nanosleep(32);
        } while (true);
    }
    __syncthreads();
    gen++;
}

__device__ __forceinline__ float d4(float4 a, float4 b)
{ return a.x*b.x + a.y*b.y + a.z*b.z + a.w*b.w; }

__device__ __forceinline__ uint64_t mkpolicy()
{
    uint64_t p;
    asm volatile("createpolicy.fractional.L2::evict_last.b64 %0, 1.0;" : "=l"(p));
    return p;
}

__device__ __forceinline__ float4 ldg_el(const float4* p, uint64_t pol)
{
    float4 v;
    asm volatile("ld.global.L2::cache_hint.v4.f32 {%0,%1,%2,%3}, [%4], %5;"
        : "=f"(v.x), "=f"(v.y), "=f"(v.z), "=f"(v.w) : "l"(p), "l"(pol));
    return v;
}

__device__ __forceinline__ void cp16(uint32_t saddr, const void* g, bool pred)
{
    asm volatile("cp.async.ca.shared.global [%0], [%1], 16, %2;"
        :: "r"(saddr), "l"(g), "r"(pred ? 16 : 0));
}

typedef wmma::fragment<wmma::matrix_a, 16,16,8, wmma::precision::tf32, wmma::row_major> FragA;
typedef wmma::fragment<wmma::matrix_b, 16,16,8, wmma::precision::tf32, wmma::row_major> FragBR;
typedef wmma::fragment<wmma::matrix_b, 16,16,8, wmma::precision::tf32, wmma::col_major> FragBC;
typedef wmma::fragment<wmma::accumulator, 16,16,8, float> FragC;

template<class F>
__device__ __forceinline__ void split_frag(F& hi, F& lo)
{
#pragma unroll
    for (int i = 0; i < hi.num_elements; i++) {
        float r = hi.x[i];
        float h = wmma::__float_to_tf32(r);
        hi.x[i] = h;
        lo.x[i] = wmma::__float_to_tf32(r - h);
    }
}

template<bool BTR>
__device__ __forceinline__ void mma_tile(float* As, float* Bs, int mrow, int nq,
                                         FragC& c0, FragC& c1)
{
#pragma unroll
    for (int kk = 0; kk < 32; kk += 8) {
        FragA ah, al;
        wmma::load_matrix_sync(ah, As + mrow*16*40 + kk, 40);
        split_frag(ah, al);
        if (!BTR) {
            FragBR b0h,b0l,b1h,b1l;
            wmma::load_matrix_sync(b0h, Bs + kk*136 + nq*32, 136);
            wmma::load_matrix_sync(b1h, Bs + kk*136 + nq*32 + 16, 136);
            split_frag(b0h, b0l); split_frag(b1h, b1l);
            wmma::mma_sync(c0, ah, b0h, c0);
            wmma::mma_sync(c0, ah, b0l, c0);
            wmma::mma_sync(c0, al, b0h, c0);
            wmma::mma_sync(c1, ah, b1h, c1);
            wmma::mma_sync(c1, ah, b1l, c1);
            wmma::mma_sync(c1, al, b1h, c1);
        } else {
            FragBC b0h,b0l,b1h,b1l;
            wmma::load_matrix_sync(b0h, Bs + (nq*32)*40 + kk, 40);
            wmma::load_matrix_sync(b1h, Bs + (nq*32+16)*40 + kk, 40);
            split_frag(b0h, b0l); split_frag(b1h, b1l);
            wmma::mma_sync(c0, ah, b0h, c0);
            wmma::mma_sync(c0, ah, b0l, c0);
            wmma::mma_sync(c0, al, b0h, c0);
            wmma::mma_sync(c1, ah, b1h, c1);
            wmma::mma_sync(c1, ah, b1l, c1);
            wmma::mma_sync(c1, al, b1h, c1);
        }
    }
}

template<bool BTR>
__device__ __forceinline__ void gemm_pipe(
    const float* __restrict__ A, int M, int K, int lda,
    const float* __restrict__ B1, const float* __restrict__ B2,
    int N1, int N, int ldb1, int ldb2,
    float* __restrict__ part, size_t slab, int ldp,
    int m0, int n0, int kt0, int kt1, float* __restrict__ smbase)
{
    const int t = threadIdx.x;
    const int warp = t >> 5, mrow = warp >> 2, nq = warp & 3;
    FragC c0, c1;
    wmma::fill_fragment(c0, 0.f);
    wmma::fill_fragment(c1, 0.f);

    auto issue = [&](int kt, int bufi) {
        float* As = smbase + bufi*BUFF;
        float* Bs = As + 1280;
        int k0 = kt*32;
        {
            int mm = t >> 3, kq = t & 7;
            int mg = m0 + mm, kg = k0 + kq*4;
            bool ok = (mg < M) && (kg < K);
            uint32_t sa = (uint32_t)__cvta_generic_to_shared(&As[mm*40 + kq*4]);
            cp16(sa, &A[(size_t)mg*lda + kg], ok);
        }
        if (!BTR) {
            int kk = t >> 3, cc = t & 7;
            int kg = k0 + kk;
#pragma unroll
            for (int j = 0; j < 4; j++) {
                int nn = (cc + 8*j)*4;
                int ng = n0 + nn;
                bool ok = (kg < K) && (ng < N);
                const float* g = (ng < N1) ? &B1[(size_t)kg*ldb1 + ng]
                                           : &B2[(size_t)kg*ldb2 + (ng - N1)];
                uint32_t sa = (uint32_t)__cvta_generic_to_shared(&Bs[kk*136 + nn]);
                cp16(sa, g, ok);
            }
        } else {
            int n = t >> 1, half = t & 1;
            int ng = n0 + n;
            bool okrow = ng < N;
            const float* brow = okrow ? ((ng < N1) ? &B1[(size_t)ng*ldb1]
                                                   : &B2[(size_t)(ng-N1)*ldb2]) : B1;
#pragma unroll
            for (int j = 0; j < 4; j++) {
                int kg = k0 + half*16 + j*4;
                bool ok = okrow && (kg < K);
                uint32_t sa = (uint32_t)__cvta_generic_to_shared(&Bs[n*40 + half*16 + j*4]);
                cp16(sa, &brow[kg], ok);
            }
        }
        asm volatile("cp.async.commit_group;");
    };

    issue(kt0, 0);
    for (int kt = kt0; kt < kt1; kt++) {
        int bufi = (kt - kt0) & 1;
        bool more = (kt + 1 < kt1);
        if (more) issue(kt + 1, bufi ^ 1);
        if (more) asm volatile("cp.async.wait_group 1;");
        else      asm volatile("cp.async.wait_group 0;");
        __syncthreads();
        float* As = smbase + bufi*BUFF;
        mma_tile<BTR>(As, As + 1280, mrow, nq, c0, c1);
        __syncthreads();
    }
    float* cb = part + slab + (size_t)(m0 + mrow*16)*ldp + n0 + nq*32;
    wmma::store_matrix_sync(cb,      c0, ldp, wmma::mem_row_major);
    wmma::store_matrix_sync(cb + 16, c1, ldp, wmma::mem_row_major);
}

template<bool REDA, bool GATEA>
__device__ __forceinline__ void gemm_w(
    const float* __restrict__ A, int M, int K, int lda,
    int Zred, size_t slabA, float ascale, const float* __restrict__ gateA,
    const float* __restrict__ B1, const float* __restrict__ B2,
    int N1, int N, int ldb1, int ldb2,
    float* __restrict__ part, size_t slab, int ldp,
    int m0, int n0, int kt0, int kt1, float* __restrict__ smbase)
{
    const int t = threadIdx.x;
    const int warp = t >> 5, mrow = warp >> 2, nq = warp & 3;
    float* As = smbase;
    float* Bs = smbase + 1280;
    FragC c0, c1;
    wmma::fill_fragment(c0, 0.f);
    wmma::fill_fragment(c1, 0.f);

    for (int kt = kt0; kt < kt1; kt++) {
        int k0 = kt*32;
        {
            int mm = t >> 3, kq = (t & 7)*4;
            int mg = m0 + mm, kg = k0 + kq;
            float4 v = make_float4(0,0,0,0);
            if (mg < M && kg + 3 < K) {
                if (REDA) {
                    for (int z = 0; z < Zred; z++) {
                        float4 w = *(const float4*)&A[(size_t)z*slabA + (size_t)mg*lda + kg];
                        v.x+=w.x; v.y+=w.y; v.z+=w.z; v.w+=w.w;
                    }
                } else v = *(const float4*)&A[(size_t)mg*lda + kg];
                v.x*=ascale; v.y*=ascale; v.z*=ascale; v.w*=ascale;
                if (GATEA) {
                    float4 g = *(const float4*)&gateA[(size_t)mg*lda + kg];
                    v.x*=g.x; v.y*=g.y; v.z*=g.z; v.w*=g.w;
                }
            } else if (mg < M) {
                float tmp[4] = {0,0,0,0};
                for (int j = 0; j < 4; j++) {
                    int k2 = kg + j;
                    if (k2 < K) {
                        float s = 0.f;
                        if (REDA) { for (int z=0; z<Zred; z++) s += A[(size_t)z*slabA + (size_t)mg*lda + k2]; }
                        else s = A[(size_t)mg*lda + k2];
                        s *= ascale;
                        if (GATEA) s *= gateA[(size_t)mg*lda + k2];
                        tmp[j] = s;
                    }
                }
                v = make_float4(tmp[0],tmp[1],tmp[2],tmp[3]);
            }
            *(float4*)&As[ (t>>3)*40 + (t&7)*4 ] = v;
        }
        {
            int kk = t >> 3, cc = t & 7;
            int kg = k0 + kk;
#pragma unroll
            for (int j = 0; j < 4; j++) {
                int nn = (cc + 8*j)*4;
                int ng = n0 + nn;
                float4 v = make_float4(0,0,0,0);
                if (kg < K && ng < N) {
                    if (ng < N1) v = *(const float4*)&B1[(size_t)kg*ldb1 + ng];
                    else         v = *(const float4*)&B2[(size_t)kg*ldb2 + (ng-N1)];
                }
                *(float4*)&Bs[kk*136 + nn] = v;
            }
        }
        __syncthreads();
        mma_tile<false>(As, Bs, mrow, nq, c0, c1);
        __syncthreads();
    }
    float* cb = part + slab + (size_t)(m0 + mrow*16)*ldp + n0 + nq*32;
    wmma::store_matrix_sync(cb,      c0, ldp, wmma::mem_row_major);
    wmma::store_matrix_sync(cb + 16, c1, ldp, wmma::mem_row_major);
}

// stage unit counts
#define U_MLP   40
#define U_QP1   320
#define S0U     (U_MLP+U_QP1)     // 360
#define U_QP2   200
#define U_AVG   256
#define S1U     (U_QP2+U_AVG)     // 456
#define U_QR    160
#define U_GATP  154
#define S2U     (U_QR+U_GATP)     // 314
#define U_GR    42                // gates reduce, float4 (BS*CATD/4/256 = 41.4)
#define U_QK    440
#define S3U     (U_GR+U_QK)       // 482
#define U_QKR   207               // qk reduce, float4 (MNk/4/256 = 206.9)

__global__ void __launch_bounds__(256, 3) fused_k(
    const float* __restrict__ sc,  const float* __restrict__ bw,
    const float* __restrict__ ss,  const float* __restrict__ bsm,
    const float* __restrict__ qf,
    const float* __restrict__ Wm1, const float* __restrict__ bm1,
    const float* __restrict__ Wm2, const float* __restrict__ bm2,
    const float* __restrict__ Wvis,const float* __restrict__ bvis,
    const float* __restrict__ Wsem,const float* __restrict__ bsem,
    const float* __restrict__ Wq,  const float* __restrict__ Wk,
    const float* __restrict__ Wv,  const float* __restrict__ Wqs,
    const float* __restrict__ Wks, const float* __restrict__ Wfc,
    const float* __restrict__ temp, float* __restrict__ outL)
{
    extern __shared__ __align__(32) float sm[];
    const int NBLK = gridDim.x;
    const int t = threadIdx.x;
    const uint64_t pol = mkpolicy();
    int gen = 1;

    // ===== S0: MLP | qp1 (sc@Wq, pipelined) =====
    for (int u = blockIdx.x; u < S0U; u += NBLK) {
        if (u < U_MLP) {
            int m0u = u * 4;
            for (int i = t; i < 4*SEM; i += 256)
                sm[i] = ss[(size_t)(m0u + i/SEM)*SEM + (i % SEM)];
            __syncthreads();
            for (int n = t; n < SEM; n += 256) {
                float a0 = bm1[n], a1 = a0, a2 = a0, a3 = a0;
                for (int k = 0; k < SEM; k++) {
                    float w = Wm1[(size_t)k*SEM + n];
                    a0 = fmaf(sm[0*SEM+k], w, a0); a1 = fmaf(sm[1*SEM+k], w, a1);
                    a2 = fmaf(sm[2*SEM+k], w, a2); a3 = fmaf(sm[3*SEM+k], w, a3);
                }
                sm[1280 + 0*SEM + n] = (a0 >= 0.f) ? a0 : 0.1f*a0;
                sm[1280 + 1*SEM + n] = (a1 >= 0.f) ? a1 : 0.1f*a1;
                sm[1280 + 2*SEM + n] = (a2 >= 0.f) ? a2 : 0.1f*a2;
                sm[1280 + 3*SEM + n] = (a3 >= 0.f) ? a3 : 0.1f*a3;
            }
            __syncthreads();
            for (int n = t; n < SEM; n += 256) {
                float a0 = bm2[n], a1 = a0, a2 = a0, a3 = a0;
                for (int k = 0; k < SEM; k++) {
                    float w = Wm2[(size_t)k*SEM + n];
                    a0 = fmaf(sm[1280+0*SEM+k], w, a0); a1 = fmaf(sm[1280+1*SEM+k], w, a1);
                    a2 = fmaf(sm[1280+2*SEM+k], w, a2); a3 = fmaf(sm[1280+3*SEM+k], w, a3);
                }
                g_scal[(size_t)(m0u+0)*SEM + n] = a0;
                g_scal[(size_t)(m0u+1)*SEM + n] = a1;
                g_scal[(size_t)(m0u+2)*SEM + n] = a2;
                g_scal[(size_t)(m0u+3)*SEM + n] = a3;
            }
            __syncthreads();
        } else {
            int uu = u - U_MLP;
            int z = uu & 7, r = uu >> 3;
            int nt = r & 7, mt = r >> 3;
            gemm_pipe<false>(sc, BTOT, FD, FD, Wq, Wq, FD, FD, FD, FD,
                g_part, (size_t)z*MNq, FD, mt*32, nt*128, z*4, z*4+4, sm);
        }
    }
    gsync(gen);

    // ===== S1: qp2 (s@Wqs, pipelined) | avg partials (evict_last) =====
    for (int u = blockIdx.x; u < S1U; u += NBLK) {
        if (u < U_QP2) {
            int z = u % 5, r = u / 5;
            int nt = r & 7, mt = r >> 3;
            gemm_pipe<false>(g_scal, BTOT, SEM, SEM, Wqs, Wqs, FD, FD, FD, FD,
                g_part, (size_t)(8+z)*MNq, FD, mt*32, nt*128, z*2, z*2+2, sm);
        } else {
            int uu = u - U_QP2;
            int chunk = uu >> 6, r = uu & 63;
            int b = r >> 1, cpart = r & 1;
            int c4 = cpart*256 + t;
            if (c4 < CATD/4) {
                int c = c4*4;
                int n0 = chunk*128;
                float4 v = make_float4(0,0,0,0);
                if (c < FD) {
                    const float4* p = (const float4*)bw + ((size_t)b*NB + n0)*(FD/4) + c4;
#pragma unroll 16
                    for (int n = 0; n < 128; n++) {
                        float4 x = ldg_el(&p[(size_t)n*(FD/4)], pol);
                        v.x+=x.x; v.y+=x.y; v.z+=x.z; v.w+=x.w;
                    }
                } else {
                    const float4* p = (const float4*)(bsm + ((size_t)b*NB + n0)*SEM + (c-FD));
#pragma unroll 16
                    for (int n = 0; n < 128; n++) {
                        float4 x = ldg_el(&p[(size_t)n*(SEM/4)], pol);
                        v.x+=x.x; v.y+=x.y; v.z+=x.z; v.w+=x.w;
                    }
                }
                *(float4*)&g_avgp[(size_t)chunk*BS*CATD + (size_t)b*CATD + c] = v;
            }
        }
    }
    gsync(gen);

    // ===== S2: q reduce | gates GEMM partials =====
    for (int u = blockIdx.x; u < S2U; u += NBLK) {
        if (u < U_QR) {
            size_t i4 = (size_t)u*256 + t;
            float4 v = make_float4(0,0,0,0);
#pragma unroll
            for (int z = 0; z < 13; z++) {
                float4 w = ((const float4*)g_part)[(size_t)z*(MNq/4) + i4];
                v.x+=w.x; v.y+=w.y; v.z+=w.z; v.w+=w.w;
            }
            ((float4*)g_q)[i4] = v;
        } else {
            int uu = u - U_QR;
            int z = uu % 14, nt = uu / 14;
            gemm_w<true,false>(g_avgp, BS, CATD, CATD, 4, (size_t)BS*CATD, 1.f/NB, nullptr,
                Wvis, Wsem, FD, CATD, FD, SEM,
                g_part2, (size_t)z*SLABG, 1408, 0, nt*128, z*3, z*3+3, sm);
        }
    }
    gsync(gen);

    // ===== S3: gates reduce (float4) | qk GEMM =====
    for (int u = blockIdx.x; u < S3U; u += NBLK) {
        if (u < U_GR) {
            size_t i4 = (size_t)u*256 + t;
            if (i4 < (size_t)BS*CATD/4) {
                int m = (int)(i4 / 331), n4 = (int)(i4 % 331);
                int n = n4*4;
                float4 v = make_float4(0,0,0,0);
#pragma unroll
                for (int z = 0; z < 14; z++) {
                    float4 w = *(const float4*)&g_part2[(size_t)z*SLABG + (size_t)m*1408 + n];
                    v.x+=w.x; v.y+=w.y; v.z+=w.z; v.w+=w.w;
                }
                if (n < FD) {
                    float4 bv = *(const float4*)&bvis[n];
                    v.x = 1.f + 1.f/(1.f + __expf(-(v.x+bv.x)));
                    v.y = 1.f + 1.f/(1.f + __expf(-(v.y+bv.y)));
                    v.z = 1.f + 1.f/(1.f + __expf(-(v.z+bv.z)));
                    v.w = 1.f + 1.f/(1.f + __expf(-(v.w+bv.w)));
                    *(float4*)&g_gv[(size_t)m*FD + n] = v;
                } else {
                    int ns = n - FD;
                    float4 bs2 = *(const float4*)&bsem[ns];
                    v.x = 1.f + 1.f/(1.f + __expf(-(v.x+bs2.x)));
                    v.y = 1.f + 1.f/(1.f + __expf(-(v.y+bs2.y)));
                    v.z = 1.f + 1.f/(1.f + __expf(-(v.z+bs2.z)));
                    v.w = 1.f + 1.f/(1.f + __expf(-(v.w+bs2.w)));
                    *(float4*)&g_gs[(size_t)m*SEM + ns] = v;
                }
            }
        } else {
            int uu = u - U_GR;
            int z = uu & 7, r = uu >> 3;
            int nt = r % 11, mt = r / 11;
            gemm_pipe<true>(g_q, BTOT, FD, FD, Wk, Wks, FD, CATD, FD, FD,
                g_part, (size_t)z*SLABK, 1408, mt*32, nt*128, z*4, z*4+4, sm);
        }
    }
    gsync(gen);

    // ===== S4: qk reduce * gates (float4, 207 units) =====
    for (int u = blockIdx.x; u < U_QKR; u += NBLK) {
        size_t i4 = (size_t)u*256 + t;
        if (i4 < (size_t)MNk/4) {
            int m = (int)(i4 / 331), n4 = (int)(i4 % 331);
            int n = n4*4;
            float4 v = make_float4(0,0,0,0);
#pragma unroll
            for (int z = 0; z < 8; z++) {
                float4 w = *(const float4*)&g_part[(size_t)z*SLABK + (size_t)m*1408 + n];
                v.x+=w.x; v.y+=w.y; v.z+=w.z; v.w+=w.w;
            }
            int b = m / NWAY;
            if (n < FD) {
                float4 g = *(const float4*)&g_gv[(size_t)b*FD + n];
                v.x*=g.x; v.y*=g.y; v.z*=g.z; v.w*=g.w;
                *(float4*)&g_qkg[(size_t)m*FD + n] = v;
            } else {
                int ns = n - FD;
                float4 g = *(const float4*)&g_gs[(size_t)b*SEM + ns];
                v.x*=g.x; v.y*=g.y; v.z*=g.z; v.w*=g.w;
                *(float4*)&g_qksg[(size_t)m*SEM + ns] = v;
            }
        }
    }
    gsync(gen);

    // ===== S5: scores (4 rows per warp, 512 units — R13 form) =====
    for (int u = blockIdx.x; u < 512; u += NBLK) {
        int b = u / 16, ch = u % 16;
        int w = t >> 5, lane = t & 31;
        int nbase = ch*32 + w*4;
        float acc[4][5];
#pragma unroll
        for (int j = 0; j < 4; j++)
#pragma unroll
            for (int p = 0; p < 5; p++) acc[j][p] = 0.f;
        const float4* qkg4 = (const float4*)g_qkg  + (size_t)b*NWAY*(FD/4);
        const float4* qks4 = (const float4*)g_qksg + (size_t)b*NWAY*(SEM/4);
        const float4* bw4  = (const float4*)bw     + (size_t)b*NB*(FD/4);
        const float4* bs4  = (const float4*)bsm    + (size_t)b*NB*(SEM/4);
#pragma unroll
        for (int tt = 0; tt < 8; tt++) {
            int c = tt*32 + lane;
            float4 qv[5];
#pragma unroll
            for (int p = 0; p < 5; p++) qv[p] = qkg4[p*(FD/4) + c];
#pragma unroll
            for (int j = 0; j < 4; j++) {
                float4 x = ldg_el(&bw4[(size_t)(nbase+j)*(FD/4) + c], pol);
#pragma unroll
                for (int p = 0; p < 5; p++) acc[j][p] += d4(x, qv[p]);
            }
        }
#pragma unroll
        for (int tt = 0; tt < 3; tt++) {
            int c = tt*32 + lane;
            bool ok = c < (SEM/4);
            float4 qv[5];
#pragma unroll
            for (int p = 0; p < 5; p++)
                qv[p] = ok ? qks4[p*(SEM/4) + c] : make_float4(0,0,0,0);
#pragma unroll
            for (int j = 0; j < 4; j++) {
                float4 x = ok ? ldg_el(&bs4[(size_t)(nbase+j)*(SEM/4) + c], pol) : make_float4(0,0,0,0);
#pragma unroll
                for (int p = 0; p < 5; p++) acc[j][p] += d4(x, qv[p]);
            }
        }
#pragma unroll
        for (int off = 16; off; off >>= 1)
#pragma unroll
            for (int j = 0; j < 4; j++)
#pragma unroll
                for (int p = 0; p < 5; p++)
                    acc[j][p] += __shfl_xor_sync(0xffffffffu, acc[j][p], off);
#pragma unroll
        for (int j = 0; j < 4; j++)
            if (lane == j) {
                int n = nbase + j;
#pragma unroll
                for (int p = 0; p < 5; p++)
                    g_scr[(size_t)(b*NWAY+p)*NB + n] = acc[j][p] * (1.f/32.f);
            }
    }
    gsync(gen);

    // ===== S6: fused softmax + nway-avg attention + mix partials (512 units) =====
    for (int u = blockIdx.x; u < 512; u += NBLK) {
        int b = u >> 4, chunk = u & 15;
        int n0 = chunk*32;
        int w = t >> 5, lane = t & 31;
        for (int i = t; i < NWAY*NB; i += 256)
            sm[i] = g_scr[(size_t)b*NWAY*NB + i];
        __syncthreads();
        float mx[5];
#pragma unroll
        for (int p = 0; p < 5; p++)
            mx[p] = fmaxf(sm[p*NB + t], sm[p*NB + 256 + t]);
#pragma unroll
        for (int off = 16; off; off >>= 1)
#pragma unroll
            for (int p = 0; p < 5; p++)
                mx[p] = fmaxf(mx[p], __shfl_xor_sync(0xffffffffu, mx[p], off));
        if (lane == 0)
#pragma unroll
            for (int p = 0; p < 5; p++) sm[2624 + w*5 + p] = mx[p];
        __syncthreads();
        if (t < 5) {
            float m = sm[2624 + t];
            for (int w2 = 1; w2 < 8; w2++) m = fmaxf(m, sm[2624 + w2*5 + t]);
            sm[2680 + t] = m;
        }
        __syncthreads();
        float sme[5];
#pragma unroll
        for (int p = 0; p < 5; p++) {
            float m = sm[2680 + p];
            sme[p] = __expf(sm[p*NB + t] - m) + __expf(sm[p*NB + 256 + t] - m);
        }
#pragma unroll
        for (int off = 16; off; off >>= 1)
#pragma unroll
            for (int p = 0; p < 5; p++)
                sme[p] += __shfl_xor_sync(0xffffffffu, sme[p], off);
        if (lane == 0)
#pragma unroll
            for (int p = 0; p < 5; p++) sm[2624 + w*5 + p] = sme[p];
        __syncthreads();
        if (t < 5) {
            float s = 0.f;
            for (int w2 = 0; w2 < 8; w2++) s += sm[2624 + w2*5 + t];
            sm[2688 + t] = 1.f / s;
        }
        __syncthreads();
        if (t < 32) {
            int n = n0 + t;
            float a = 0.f;
#pragma unroll
            for (int p = 0; p < 5; p++)
                a += __expf(sm[p*NB + n] - sm[2680 + p]) * sm[2688 + p];
            sm[2696 + t] = a * (1.f/NWAY);
        }
        __syncthreads();
        float4 acc = make_float4(0,0,0,0);
        const float4* p4 = (const float4*)bw + ((size_t)b*NB + n0)*(FD/4) + t;
#pragma unroll 16
        for (int r = 0; r < 32; r++) {
            float4 x = p4[(size_t)r*(FD/4)];
            float a = sm[2696 + r];
            acc.x = fmaf(x.x, a, acc.x); acc.y = fmaf(x.y, a, acc.y);
            acc.z = fmaf(x.z, a, acc.z); acc.w = fmaf(x.w, a, acc.w);
        }
        ((float4*)g_mixp)[(size_t)chunk*(SLABF/4) + (size_t)b*(FD/4) + t] = acc;
        __syncthreads();
    }
    gsync(gen);

    // ===== S7: fakev = (mixavg * gv) @ Wv, split-K 32 (256 units) =====
    for (int u = blockIdx.x; u < 256; u += NBLK) {
        int z = u & 31, nt = u >> 5;
        gemm_w<true,true>(g_mixp, BS, FD, FD, 16, (size_t)SLABF, 1.f, g_gv,
            Wv, Wv, FD, FD, FD, FD,
            g_part, (size_t)z*SLABF, FD, 0, nt*128, z, z+1, sm);
    }
    gsync(gen);

    // ===== S8: fakefc = reduce(fakev) @ Wfc, split-K 32 (slabs 32..63) =====
    for (int u = blockIdx.x; u < 256; u += NBLK) {
        int z = u & 31, nt = u >> 5;
        gemm_w<true,false>(g_part, BS, FD, FD, 32, (size_t)SLABF, 1.f, nullptr,
            Wfc, Wfc, FD, FD, FD, FD,
            g_part, (size_t)(32+z)*SLABF, FD, 0, nt*128, z, z+1, sm);
    }
    gsync(gen);

    // ===== S9: fake + norms + logits =====
    for (int u = blockIdx.x; u < BS*10; u += NBLK) {
        int b = u / 10, qc = u % 10;
        {
            const float4* sc4 = (const float4*)sc + (size_t)b*NWAY*(FD/4);
            float4 f = make_float4(0,0,0,0);
            float sq[6];
#pragma unroll
            for (int c = 0; c < NWAY; c++) {
                float4 o = sc4[c*(FD/4) + t];
                sq[c] = d4(o, o);
                f.x+=o.x; f.y+=o.y; f.z+=o.z; f.w+=o.w;
            }
            f.x*=0.2f; f.y*=0.2f; f.z*=0.2f; f.w*=0.2f;
#pragma unroll
            for (int z = 32; z < 64; z++) {
                float4 w2 = ((const float4*)g_part)[(size_t)z*(SLABF/4) + (size_t)b*(FD/4) + t];
                f.x+=w2.x; f.y+=w2.y; f.z+=w2.z; f.w+=w2.w;
            }
            ((float4*)sm)[t] = f;
            sq[5] = d4(f, f);
#pragma unroll
            for (int off = 16; off; off >>= 1)
#pragma unroll
                for (int r = 0; r < 6; r++)
                    sq[r] += __shfl_xor_sync(0xffffffffu, sq[r], off);
            int lane = t & 31, w = t >> 5;
            if (lane == 0)
#pragma unroll
                for (int r = 0; r < 6; r++) sm[1024 + w*6 + r] = sq[r];
            __syncthreads();
            if (t < 6) {
                float s = 0.f;
                for (int w2 = 0; w2 < 8; w2++) s += sm[1024 + w2*6 + t];
                sm[1072 + t] = 1.f / sqrtf(s);
            }
            __syncthreads();
        }
        {
            int w = t >> 5, lane = t & 31;
            int iq = qc*8 + w;
            if (iq < NQ) {
                const float4* q4  = (const float4*)qf + ((size_t)b*NQ + iq)*(FD/4);
                const float4* sc4 = (const float4*)sc + (size_t)b*NWAY*(FD/4);
                const float4* f4  = (const float4*)sm;
                float qq = 0.f, d[6] = {0,0,0,0,0,0};
                for (int i = lane; i < FD/4; i += 32) {
                    float4 x = q4[i];
                    qq += d4(x, x);
#pragma unroll
                    for (int r = 0; r < NWAY; r++) d[r] += d4(x, sc4[r*(FD/4) + i]);
                    d[5] += d4(x, f4[i]);
                }
#pragma unroll
                for (int off = 16; off; off >>= 1) {
                    qq += __shfl_xor_sync(0xffffffffu, qq, off);
#pragma unroll
                    for (int r = 0; r < 6; r++) d[r] += __shfl_xor_sync(0xffffffffu, d[r], off);
                }
                if (lane == 0) {
                    float s = temp[0] / sqrtf(qq);
                    float* o = outL + ((size_t)b*NQ + iq)*6;
#pragma unroll
                    for (int r = 0; r < 6; r++) o[r] = d[r] * s * sm[1072 + r];
                }
            }
        }
        __syncthreads();
    }
}

// ---------------- host ----------------
extern "C" void kernel_launch(void* const* d_in, const int* in_sizes, int n_in,
                              void* d_out, int out_size)
{
    const float* sc   = (const float*)d_in[0];
    const float* bw   = (const float*)d_in[1];
    const float* ss   = (const float*)d_in[2];
    const float* bsm  = (const float*)d_in[3];
    const float* qf   = (const float*)d_in[4];
    const float* Wm1  = (const float*)d_in[5];
    const float* bm1  = (const float*)d_in[6];
    const float* Wm2  = (const float*)d_in[7];
    const float* bm2  = (const float*)d_in[8];
    const float* Wvis = (const float*)d_in[9];
    const float* bvis = (const float*)d_in[10];
    const float* Wsem = (const float*)d_in[11];
    const float* bsem = (const float*)d_in[12];
    const float* Wq   = (const float*)d_in[13];
    const float* Wk   = (const float*)d_in[14];
    const float* Wv   = (const float*)d_in[15];
    const float* Wqs  = (const float*)d_in[16];
    const float* Wks  = (const float*)d_in[17];
    const float* Wfc  = (const float*)d_in[18];
    const float* temp = (const float*)d_in[19];
    float* out = (float*)d_out;

    const int smem_bytes = SMEMF * sizeof(float);  // 51200
    cudaFuncSetAttribute(fused_k, cudaFuncAttributeMaxDynamicSharedMemorySize, smem_bytes);

    int dev = 0;
    cudaGetDevice(&dev);
    int nsm = 148;
    cudaDeviceGetAttribute(&nsm, cudaDevAttrMultiProcessorCount, dev);
    int bpm = 1;
    cudaOccupancyMaxActiveBlocksPerMultiprocessor(&bpm, fused_k, 256, smem_bytes);
    if (bpm < 1) bpm = 1;
    int nblk = nsm * bpm;

    void* barp = nullptr;
    cudaGetSymbolAddress(&barp, g_barrier);
    cudaMemsetAsync(barp, 0, sizeof(unsigned int), 0);

    fused_k<<<nblk, 256, smem_bytes>>>(sc, bw, ss, bsm, qf, Wm1, bm1, Wm2, bm2,
                                       Wvis, bvis, Wsem, bsem, Wq, Wk, Wv, Wqs, Wks, Wfc,
                                       temp, out);
}